// round 9
// baseline (speedup 1.0000x reference)
#include <cuda_runtime.h>
#include <cuda_bf16.h>
#include <math.h>
#include <stdint.h>

#define NB 2
#define NT 2048
#define NC 768
#define NH 12
#define ND 64

// ---------------------------------------------------------------------------
// Device-global scratch (allocation-free rule)
// ---------------------------------------------------------------------------
__device__ float g_q[NB*NH*NT*ND];   // [b][h][t][d] fp32
__device__ float g_k[NB*NH*NT*ND];
__device__ float g_v[NB*NH*NT*ND];

__device__ __align__(16) __nv_bfloat16 g_xH[NB*NT*NC];
__device__ __align__(16) __nv_bfloat16 g_xL[NB*NT*NC];
__device__ __align__(16) __nv_bfloat16 g_waH[3*NC*NC];
__device__ __align__(16) __nv_bfloat16 g_waL[3*NC*NC];
__device__ __align__(16) __nv_bfloat16 g_wpH[NC*NC];
__device__ __align__(16) __nv_bfloat16 g_wpL[NC*NC];
__device__ __align__(16) __nv_bfloat16 g_yH[NB*NT*NC];
__device__ __align__(16) __nv_bfloat16 g_yL[NB*NT*NC];

// ---------------------------------------------------------------------------
// helpers
// ---------------------------------------------------------------------------
__device__ __forceinline__ uint32_t smem_to_u32(const void* p) {
    uint32_t a;
    asm("{ .reg .u64 t; cvta.to.shared.u64 t, %1; cvt.u32.u64 %0, t; }"
        : "=r"(a) : "l"(p));
    return a;
}

__device__ __forceinline__ void cp_async16(uint32_t saddr, const void* gptr) {
    asm volatile("cp.async.cg.shared.global [%0], [%1], 16;"
                 :: "r"(saddr), "l"(gptr) : "memory");
}
__device__ __forceinline__ void cp_commit() {
    asm volatile("cp.async.commit_group;" ::: "memory");
}
__device__ __forceinline__ void cp_wait0() {
    asm volatile("cp.async.wait_group 0;" ::: "memory");
}

__device__ __forceinline__ void lm4(uint32_t addr, unsigned r[4]) {
    asm volatile("ldmatrix.sync.aligned.m8n8.x4.shared.b16 {%0,%1,%2,%3}, [%4];"
        : "=r"(r[0]), "=r"(r[1]), "=r"(r[2]), "=r"(r[3]) : "r"(addr));
}

// D += A*B, m16n8k8 tf32 (operands: fp32 bit patterns; HW uses tf32 field)
__device__ __forceinline__ void mma_tf32(float c[4], const unsigned a[4],
                                         unsigned b0, unsigned b1) {
    asm volatile(
        "mma.sync.aligned.m16n8k8.row.col.f32.tf32.tf32.f32 "
        "{%0,%1,%2,%3},{%4,%5,%6,%7},{%8,%9},{%0,%1,%2,%3};\n"
        : "+f"(c[0]), "+f"(c[1]), "+f"(c[2]), "+f"(c[3])
        : "r"(a[0]), "r"(a[1]), "r"(a[2]), "r"(a[3]), "r"(b0), "r"(b1));
}

// D += A*B, m16n8k16 bf16
__device__ __forceinline__ void mma_bf16(float c[4], const unsigned a[4],
                                         unsigned b0, unsigned b1) {
    asm volatile(
        "mma.sync.aligned.m16n8k16.row.col.f32.bf16.bf16.f32 "
        "{%0,%1,%2,%3},{%4,%5,%6,%7},{%8,%9},{%0,%1,%2,%3};\n"
        : "+f"(c[0]), "+f"(c[1]), "+f"(c[2]), "+f"(c[3])
        : "r"(a[0]), "r"(a[1]), "r"(a[2]), "r"(a[3]), "r"(b0), "r"(b1));
}

// ---------------------------------------------------------------------------
// Split fp32 -> (bf16 hi, bf16 lo). which: 0=x, 1=Wa, 2=Wp
// ---------------------------------------------------------------------------
__global__ void split_bf(const float* __restrict__ s, int which) {
    __nv_bfloat16 *dH, *dL;
    if (which == 0)      { dH = g_xH;  dL = g_xL;  }
    else if (which == 1) { dH = g_waH; dL = g_waL; }
    else                 { dH = g_wpH; dL = g_wpL; }
    int i4 = (blockIdx.x * 256 + threadIdx.x) * 4;
    float4 v = *(const float4*)(s + i4);
    __nv_bfloat16 h0 = __float2bfloat16_rn(v.x);
    __nv_bfloat16 h1 = __float2bfloat16_rn(v.y);
    __nv_bfloat16 h2 = __float2bfloat16_rn(v.z);
    __nv_bfloat16 h3 = __float2bfloat16_rn(v.w);
    ((__nv_bfloat162*)(dH + i4))[0] = __halves2bfloat162(h0, h1);
    ((__nv_bfloat162*)(dH + i4))[1] = __halves2bfloat162(h2, h3);
    ((__nv_bfloat162*)(dL + i4))[0] = __halves2bfloat162(
        __float2bfloat16_rn(v.x - __bfloat162float(h0)),
        __float2bfloat16_rn(v.y - __bfloat162float(h1)));
    ((__nv_bfloat162*)(dL + i4))[1] = __halves2bfloat162(
        __float2bfloat16_rn(v.z - __bfloat162float(h2)),
        __float2bfloat16_rn(v.w - __bfloat162float(h3)));
}

// ---------------------------------------------------------------------------
// 3xBF16 NT GEMM: pre-split bf16, cp.async double-buffered, ldmatrix frags.
// BM=128, BN=64, BK=32, 256 threads = 8 warps (4m x 2n), warp tile 32x32.
// ---------------------------------------------------------------------------
#define A_STG (128 * 40)
#define B_STG (64 * 40)
#define U_AH 0
#define U_AL (2 * A_STG)
#define U_BH (4 * A_STG)
#define U_BL (4 * A_STG + 2 * B_STG)
#define GEMM_SMEM ((4 * A_STG + 4 * B_STG) * 2)   // 61440 bytes

__device__ __forceinline__ void scat_qkv(int m, int n, float v0, float v1) {
    int b = m >> 11;
    int t = m & 2047;
    int which = n / NC;
    int r = n - which * NC;
    int h = r >> 6;
    int d = r & 63;
    float* dst = (which == 0) ? g_q : (which == 1) ? g_k : g_v;
    *(float2*)(dst + (((size_t)b * NH + h) * NT + t) * ND + d) = make_float2(v0, v1);
}

template<int MODE>
__global__ void __launch_bounds__(256, 2)
gemm3bf(float* __restrict__ Cout, int K, int N)
{
    extern __shared__ __align__(16) unsigned short us[];

    const __nv_bfloat16* AH = (MODE == 0) ? g_xH  : g_yH;
    const __nv_bfloat16* AL = (MODE == 0) ? g_xL  : g_yL;
    const __nv_bfloat16* BH = (MODE == 0) ? g_waH : g_wpH;
    const __nv_bfloat16* BL = (MODE == 0) ? g_waL : g_wpL;

    const uint32_t sb = smem_to_u32(us);
    const int m0 = blockIdx.y * 128;
    const int n0 = blockIdx.x * 64;
    const int tid = threadIdx.x;
    const int wid = tid >> 5, lane = tid & 31;
    const int g = lane >> 2, t = lane & 3;
    const int wm = wid >> 1, wn = wid & 1;

    const int arow0 = tid >> 2;
    const int ac8   = (tid & 3) * 8;
    const int brow  = tid >> 2;
    const int bc8   = (tid & 3) * 8;

    // ldmatrix per-lane address components
    const int a_lm_row = lane & 15;                       // rows 0-15 of 16-row tile
    const int a_lm_c8  = (lane >> 4) << 3;                // k-half select
    const int b_lm_row = (lane & 7) + ((lane >> 4) << 3); // 0-7 / 8-15
    const int b_lm_c8  = ((lane >> 3) & 1) << 3;          // k-half select

    auto load_stage = [&](int s, int k0) {
        #pragma unroll
        for (int i = 0; i < 2; i++) {
            int row = arow0 + i * 64;
            uint32_t so = (uint32_t)(row * 40 + ac8) * 2;
            size_t ga = (size_t)(m0 + row) * K + k0 + ac8;
            cp_async16(sb + (U_AH + s * A_STG) * 2 + so, AH + ga);
            cp_async16(sb + (U_AL + s * A_STG) * 2 + so, AL + ga);
        }
        {
            uint32_t so = (uint32_t)(brow * 40 + bc8) * 2;
            size_t gb = (size_t)(n0 + brow) * K + k0 + bc8;
            cp_async16(sb + (U_BH + s * B_STG) * 2 + so, BH + gb);
            cp_async16(sb + (U_BL + s * B_STG) * 2 + so, BL + gb);
        }
        cp_commit();
    };

    float acc[2][4][4];
    #pragma unroll
    for (int mt = 0; mt < 2; mt++)
        #pragma unroll
        for (int nt = 0; nt < 4; nt++)
            #pragma unroll
            for (int i = 0; i < 4; i++) acc[mt][nt][i] = 0.0f;

    const int NK = K / 32;
    load_stage(0, 0);

    for (int c = 0; c < NK; c++) {
        cp_wait0();
        __syncthreads();
        if (c + 1 < NK) load_stage((c + 1) & 1, (c + 1) * 32);

        const uint32_t uAH = (U_AH + (c & 1) * A_STG);
        const uint32_t uAL = (U_AL + (c & 1) * A_STG);
        const uint32_t uBH = (U_BH + (c & 1) * B_STG);
        const uint32_t uBL = (U_BL + (c & 1) * B_STG);

        #pragma unroll
        for (int ks = 0; ks < 2; ks++) {
            const int ko = ks * 16;
            unsigned aH[2][4], aL[2][4], bHq[2][4], bLq[2][4];
            #pragma unroll
            for (int mt = 0; mt < 2; mt++) {
                uint32_t ar = (uint32_t)((wm * 32 + mt * 16 + a_lm_row) * 40
                                         + ko + a_lm_c8);
                lm4(sb + (uAH + ar) * 2, aH[mt]);
                lm4(sb + (uAL + ar) * 2, aL[mt]);
            }
            #pragma unroll
            for (int np = 0; np < 2; np++) {
                uint32_t br = (uint32_t)((wn * 32 + np * 16 + b_lm_row) * 40
                                         + ko + b_lm_c8);
                lm4(sb + (uBH + br) * 2, bHq[np]);
                lm4(sb + (uBL + br) * 2, bLq[np]);
            }
            #pragma unroll
            for (int mt = 0; mt < 2; mt++)
                #pragma unroll
                for (int np = 0; np < 2; np++) {
                    mma_bf16(acc[mt][2*np],   aH[mt], bHq[np][0], bHq[np][1]);
                    mma_bf16(acc[mt][2*np+1], aH[mt], bHq[np][2], bHq[np][3]);
                    mma_bf16(acc[mt][2*np],   aH[mt], bLq[np][0], bLq[np][1]);
                    mma_bf16(acc[mt][2*np+1], aH[mt], bLq[np][2], bLq[np][3]);
                    mma_bf16(acc[mt][2*np],   aL[mt], bHq[np][0], bHq[np][1]);
                    mma_bf16(acc[mt][2*np+1], aL[mt], bHq[np][2], bHq[np][3]);
                }
        }
        __syncthreads();
    }

    #pragma unroll
    for (int mt = 0; mt < 2; mt++) {
        int r0 = m0 + wm * 32 + mt * 16 + g;
        int r1 = r0 + 8;
        #pragma unroll
        for (int nt = 0; nt < 4; nt++) {
            int c = n0 + wn * 32 + nt * 8 + 2 * t;
            if (MODE == 0) {
                scat_qkv(r0, c, acc[mt][nt][0], acc[mt][nt][1]);
                scat_qkv(r1, c, acc[mt][nt][2], acc[mt][nt][3]);
            } else {
                *(float2*)(Cout + (size_t)r0 * N + c) =
                    make_float2(acc[mt][nt][0], acc[mt][nt][1]);
                *(float2*)(Cout + (size_t)r1 * N + c) =
                    make_float2(acc[mt][nt][2], acc[mt][nt][3]);
            }
        }
    }
}

// ---------------------------------------------------------------------------
// Flash attention, tf32 mma.sync.
// Q in registers; K/V cp.async double-buffered (raw fp32 -> tf32 truncation);
// one __syncthreads per K-tile. 256 threads; Q tile 128 (16/warp); K/V tile 64.
// smem u32 layout: [stage0: K 64x68 | V 64x72][stage1: same][P 128x68]
// (Q staged through stage1 region before the pipeline starts.)
// ---------------------------------------------------------------------------
#define KV_K 0
#define KV_V (64 * 68)
#define KV_STG (64 * 68 + 64 * 72)     // 8960 u32
#define P_OFF (2 * KV_STG)
#define ATTN_U (P_OFF + 128 * 68)
#define ATTN_SMEM (ATTN_U * 4)          // 106496 bytes

__global__ void __launch_bounds__(256, 2) attn_mma()
{
    extern __shared__ __align__(16) unsigned su[];
    const uint32_t sb = smem_to_u32(su);

    const int qt = (int)gridDim.x - 1 - (int)blockIdx.x;
    const int bh = blockIdx.y;
    const int b = bh / NH;
    const int h = bh - b * NH;
    const int tid = threadIdx.x;
    const int wid = tid >> 5, lane = tid & 31;
    const int g = lane >> 2, t = lane & 3;
    const int R = wid * 16;

    const size_t head_base = ((size_t)b * NH + h) * (size_t)NT * ND;
    const int q0 = qt * 128;

    // ---- stage Q (raw fp32) through stage-1 region, pick up frags ----
    {
        unsigned* Qt = su + KV_STG;
        const float* qg = g_q + head_base + (size_t)q0 * ND;
        #pragma unroll
        for (int i = 0; i < 8; i++) {
            int idx = tid + i * 256;
            int row = idx >> 4, d4 = (idx & 15) << 2;
            *(uint4*)(Qt + row * 68 + d4) = *(const uint4*)(qg + row * ND + d4);
        }
    }
    __syncthreads();
    unsigned qa[8][4];
    {
        const unsigned* Qt = su + KV_STG;
        #pragma unroll
        for (int ks = 0; ks < 8; ks++) {
            int ra = (R + g) * 68 + ks * 8 + t;
            int rb = (R + g + 8) * 68 + ks * 8 + t;
            qa[ks][0] = Qt[ra];
            qa[ks][1] = Qt[rb];
            qa[ks][2] = Qt[ra + 4];
            qa[ks][3] = Qt[rb + 4];
        }
    }

    const int kt_max = 2 * qt + 1;

    auto issue_kv = [&](int s, int k0) {
        const float* kg = g_k + head_base + (size_t)k0 * ND;
        const float* vg = g_v + head_base + (size_t)k0 * ND;
        #pragma unroll
        for (int i = 0; i < 4; i++) {
            int idx = tid + i * 256;
            int row = idx >> 4, c4 = (idx & 15) << 2;
            cp_async16(sb + (uint32_t)(s * KV_STG + KV_K + row * 68 + c4) * 4,
                       kg + row * ND + c4);
            cp_async16(sb + (uint32_t)(s * KV_STG + KV_V + row * 72 + c4) * 4,
                       vg + row * ND + c4);
        }
        cp_commit();
    };

    // prologue: stage 0 (writes buffer 0, disjoint from the Q staging region)
    issue_kv(0, 0);

    float mrow[2] = {-1e30f, -1e30f};
    float lrow[2] = {0.0f, 0.0f};
    float o[8][4];
    #pragma unroll
    for (int nt = 0; nt < 8; nt++)
        #pragma unroll
        for (int i = 0; i < 4; i++) o[nt][i] = 0.0f;

    unsigned* Ps = su + P_OFF;

    for (int kt = 0; kt <= kt_max; kt++) {
        cp_wait0();
        __syncthreads();   // stage kt visible; all reads of the other buffer done
        if (kt + 1 <= kt_max) issue_kv((kt + 1) & 1, (kt + 1) * 64);

        const unsigned* Ks = su + (kt & 1) * KV_STG + KV_K;
        const unsigned* Vs = su + (kt & 1) * KV_STG + KV_V;
        const int k0 = kt * 64;

        // ---- S = Q K^T ----
        float sc[8][4];
        #pragma unroll
        for (int nt = 0; nt < 8; nt++)
            #pragma unroll
            for (int i = 0; i < 4; i++) sc[nt][i] = 0.0f;

        #pragma unroll
        for (int ks = 0; ks < 8; ks++) {
            #pragma unroll
            for (int nt = 0; nt < 8; nt++) {
                int kb = (nt * 8 + g) * 68 + ks * 8 + t;
                mma_tf32(sc[nt], qa[ks], Ks[kb], Ks[kb + 4]);
            }
        }

        // ---- scale + causal mask ----
        const bool nm = (kt >= 2 * qt);
        const int rlo = q0 + R + g;
        const int rhi = rlo + 8;
        #pragma unroll
        for (int nt = 0; nt < 8; nt++) {
            int cc = k0 + nt * 8 + 2 * t;
            sc[nt][0] *= 0.125f; sc[nt][1] *= 0.125f;
            sc[nt][2] *= 0.125f; sc[nt][3] *= 0.125f;
            if (nm) {
                if (cc > rlo)     sc[nt][0] = -1e30f;
                if (cc + 1 > rlo) sc[nt][1] = -1e30f;
                if (cc > rhi)     sc[nt][2] = -1e30f;
                if (cc + 1 > rhi) sc[nt][3] = -1e30f;
            }
        }

        // ---- online softmax ----
        float mx0 = -1e30f, mx1 = -1e30f;
        #pragma unroll
        for (int nt = 0; nt < 8; nt++) {
            mx0 = fmaxf(mx0, fmaxf(sc[nt][0], sc[nt][1]));
            mx1 = fmaxf(mx1, fmaxf(sc[nt][2], sc[nt][3]));
        }
        mx0 = fmaxf(mx0, __shfl_xor_sync(0xffffffffu, mx0, 1));
        mx0 = fmaxf(mx0, __shfl_xor_sync(0xffffffffu, mx0, 2));
        mx1 = fmaxf(mx1, __shfl_xor_sync(0xffffffffu, mx1, 1));
        mx1 = fmaxf(mx1, __shfl_xor_sync(0xffffffffu, mx1, 2));

        float mn0 = fmaxf(mrow[0], mx0);
        float mn1 = fmaxf(mrow[1], mx1);
        float al0 = __expf(mrow[0] - mn0);
        float al1 = __expf(mrow[1] - mn1);
        mrow[0] = mn0; mrow[1] = mn1;

        float rs0 = 0.0f, rs1 = 0.0f;
        #pragma unroll
        for (int nt = 0; nt < 8; nt++) {
            sc[nt][0] = __expf(sc[nt][0] - mn0); rs0 += sc[nt][0];
            sc[nt][1] = __expf(sc[nt][1] - mn0); rs0 += sc[nt][1];
            sc[nt][2] = __expf(sc[nt][2] - mn1); rs1 += sc[nt][2];
            sc[nt][3] = __expf(sc[nt][3] - mn1); rs1 += sc[nt][3];
        }
        rs0 += __shfl_xor_sync(0xffffffffu, rs0, 1);
        rs0 += __shfl_xor_sync(0xffffffffu, rs0, 2);
        rs1 += __shfl_xor_sync(0xffffffffu, rs1, 1);
        rs1 += __shfl_xor_sync(0xffffffffu, rs1, 2);
        lrow[0] = lrow[0] * al0 + rs0;
        lrow[1] = lrow[1] * al1 + rs1;

        #pragma unroll
        for (int nt = 0; nt < 8; nt++) {
            o[nt][0] *= al0; o[nt][1] *= al0;
            o[nt][2] *= al1; o[nt][3] *= al1;
        }

        // ---- P -> smem (raw fp32 bits), own rows only ----
        #pragma unroll
        for (int nt = 0; nt < 8; nt++) {
            int pa = (R + g) * 68 + nt * 8 + 2 * t;
            int pb = (R + g + 8) * 68 + nt * 8 + 2 * t;
            *(uint2*)(Ps + pa) = make_uint2(__float_as_uint(sc[nt][0]),
                                            __float_as_uint(sc[nt][1]));
            *(uint2*)(Ps + pb) = make_uint2(__float_as_uint(sc[nt][2]),
                                            __float_as_uint(sc[nt][3]));
        }
        __syncwarp();

        // ---- O += P V ----
        #pragma unroll
        for (int ks = 0; ks < 8; ks++) {
            unsigned a[4];
            int ra = (R + g) * 68 + ks * 8 + t;
            int rb = (R + g + 8) * 68 + ks * 8 + t;
            a[0] = Ps[ra]; a[1] = Ps[rb]; a[2] = Ps[ra + 4]; a[3] = Ps[rb + 4];
            #pragma unroll
            for (int nt = 0; nt < 8; nt++) {
                int v0 = (ks * 8 + t) * 72 + nt * 8 + g;
                int v1 = (ks * 8 + t + 4) * 72 + nt * 8 + g;
                mma_tf32(o[nt], a, Vs[v0], Vs[v1]);
            }
        }
    }

    // ---- epilogue: normalize; emit bf16 hi/lo for the proj GEMM ----
    float i0 = 1.0f / lrow[0];
    float i1 = 1.0f / lrow[1];
    size_t base0 = ((size_t)b * NT + (q0 + R + g)) * NC + h * ND;
    size_t base1 = ((size_t)b * NT + (q0 + R + g + 8)) * NC + h * ND;
    #pragma unroll
    for (int nt = 0; nt < 8; nt++) {
        size_t off0 = base0 + nt * 8 + 2 * t;
        size_t off1 = base1 + nt * 8 + 2 * t;
        float v0 = o[nt][0] * i0, v1 = o[nt][1] * i0;
        float v2 = o[nt][2] * i1, v3 = o[nt][3] * i1;
        __nv_bfloat16 h0 = __float2bfloat16_rn(v0);
        __nv_bfloat16 h1 = __float2bfloat16_rn(v1);
        __nv_bfloat16 h2 = __float2bfloat16_rn(v2);
        __nv_bfloat16 h3 = __float2bfloat16_rn(v3);
        *(__nv_bfloat162*)(g_yH + off0) = __halves2bfloat162(h0, h1);
        *(__nv_bfloat162*)(g_yH + off1) = __halves2bfloat162(h2, h3);
        *(__nv_bfloat162*)(g_yL + off0) = __halves2bfloat162(
            __float2bfloat16_rn(v0 - __bfloat162float(h0)),
            __float2bfloat16_rn(v1 - __bfloat162float(h1)));
        *(__nv_bfloat162*)(g_yL + off1) = __halves2bfloat162(
            __float2bfloat16_rn(v2 - __bfloat162float(h2)),
            __float2bfloat16_rn(v3 - __bfloat162float(h3)));
    }
}

// ---------------------------------------------------------------------------
extern "C" void kernel_launch(void* const* d_in, const int* in_sizes, int n_in,
                              void* d_out, int out_size)
{
    const float* x  = nullptr;   // 3145728
    const float* Wa = nullptr;   // 1769472
    const float* Wp = nullptr;   // 589824
    for (int i = 0; i < n_in; i++) {
        if (in_sizes[i] == NB * NT * NC)      x  = (const float*)d_in[i];
        else if (in_sizes[i] == 3 * NC * NC)  Wa = (const float*)d_in[i];
        else if (in_sizes[i] == NC * NC)      Wp = (const float*)d_in[i];
    }
    float* out = (float*)d_out;

    cudaFuncSetAttribute(attn_mma,
                         cudaFuncAttributeMaxDynamicSharedMemorySize, ATTN_SMEM);
    cudaFuncSetAttribute(gemm3bf<0>,
                         cudaFuncAttributeMaxDynamicSharedMemorySize, GEMM_SMEM);
    cudaFuncSetAttribute(gemm3bf<1>,
                         cudaFuncAttributeMaxDynamicSharedMemorySize, GEMM_SMEM);

    // 0) one-time hi/lo bf16 splits
    split_bf<<<(NB * NT * NC) / 1024, 256>>>(x, 0);
    split_bf<<<(3 * NC * NC) / 1024, 256>>>(Wa, 1);
    split_bf<<<(NC * NC) / 1024, 256>>>(Wp, 2);

    // 1) QKV projection, scatter q/k/v
    gemm3bf<0><<<dim3(3 * NC / 64, NB * NT / 128), 256, GEMM_SMEM>>>(nullptr, NC, 3 * NC);

    // 2) causal flash attention -> yH/yL bf16
    attn_mma<<<dim3(NT / 128, NB * NH), 256, ATTN_SMEM>>>();

    // 3) output projection
    gemm3bf<1><<<dim3(NC / 64, NB * NT / 128), 256, GEMM_SMEM>>>(out, NC, NC);
}

// round 10
// speedup vs baseline: 1.4676x; 1.4676x over previous
#include <cuda_runtime.h>
#include <cuda_bf16.h>
#include <math.h>
#include <stdint.h>

#define NB 2
#define NT 2048
#define NC 768
#define NH 12
#define ND 64

// ---------------------------------------------------------------------------
// Device-global scratch (allocation-free rule)
// ---------------------------------------------------------------------------
__device__ float g_q[NB*NH*NT*ND];   // [b][h][t][d] fp32
__device__ float g_k[NB*NH*NT*ND];
__device__ float g_v[NB*NH*NT*ND];

__device__ __align__(16) __nv_bfloat16 g_xH[NB*NT*NC];
__device__ __align__(16) __nv_bfloat16 g_xL[NB*NT*NC];
__device__ __align__(16) __nv_bfloat16 g_waH[3*NC*NC];
__device__ __align__(16) __nv_bfloat16 g_waL[3*NC*NC];
__device__ __align__(16) __nv_bfloat16 g_wpH[NC*NC];
__device__ __align__(16) __nv_bfloat16 g_wpL[NC*NC];
__device__ __align__(16) __nv_bfloat16 g_yH[NB*NT*NC];
__device__ __align__(16) __nv_bfloat16 g_yL[NB*NT*NC];

// ---------------------------------------------------------------------------
// helpers
// ---------------------------------------------------------------------------
__device__ __forceinline__ uint32_t smem_to_u32(const void* p) {
    uint32_t a;
    asm("{ .reg .u64 t; cvta.to.shared.u64 t, %1; cvt.u32.u64 %0, t; }"
        : "=r"(a) : "l"(p));
    return a;
}

__device__ __forceinline__ void cp_async16(uint32_t saddr, const void* gptr) {
    asm volatile("cp.async.cg.shared.global [%0], [%1], 16;"
                 :: "r"(saddr), "l"(gptr) : "memory");
}
__device__ __forceinline__ void cp_commit() {
    asm volatile("cp.async.commit_group;" ::: "memory");
}
__device__ __forceinline__ void cp_wait0() {
    asm volatile("cp.async.wait_group 0;" ::: "memory");
}

__device__ __forceinline__ unsigned f2tf32(float x) {
    unsigned r;
    asm("cvt.rna.tf32.f32 %0, %1;" : "=r"(r) : "f"(x));
    return r;
}

// D += A*B, m16n8k8 tf32 (operands: tf32 or raw fp32 bit patterns)
__device__ __forceinline__ void mma_tf32(float c[4], const unsigned a[4],
                                         unsigned b0, unsigned b1) {
    asm volatile(
        "mma.sync.aligned.m16n8k8.row.col.f32.tf32.tf32.f32 "
        "{%0,%1,%2,%3},{%4,%5,%6,%7},{%8,%9},{%0,%1,%2,%3};\n"
        : "+f"(c[0]), "+f"(c[1]), "+f"(c[2]), "+f"(c[3])
        : "r"(a[0]), "r"(a[1]), "r"(a[2]), "r"(a[3]), "r"(b0), "r"(b1));
}

// D += A*B, m16n8k16 bf16
__device__ __forceinline__ void mma_bf16(float c[4], const unsigned a[4],
                                         unsigned b0, unsigned b1) {
    asm volatile(
        "mma.sync.aligned.m16n8k16.row.col.f32.bf16.bf16.f32 "
        "{%0,%1,%2,%3},{%4,%5,%6,%7},{%8,%9},{%0,%1,%2,%3};\n"
        : "+f"(c[0]), "+f"(c[1]), "+f"(c[2]), "+f"(c[3])
        : "r"(a[0]), "r"(a[1]), "r"(a[2]), "r"(a[3]), "r"(b0), "r"(b1));
}

// ---------------------------------------------------------------------------
// Split fp32 -> (bf16 hi, bf16 lo). which: 0=x, 1=Wa, 2=Wp
// ---------------------------------------------------------------------------
__global__ void split_bf(const float* __restrict__ s, int which) {
    __nv_bfloat16 *dH, *dL;
    if (which == 0)      { dH = g_xH;  dL = g_xL;  }
    else if (which == 1) { dH = g_waH; dL = g_waL; }
    else                 { dH = g_wpH; dL = g_wpL; }
    int i4 = (blockIdx.x * 256 + threadIdx.x) * 4;
    float4 v = *(const float4*)(s + i4);
    __nv_bfloat16 h0 = __float2bfloat16_rn(v.x);
    __nv_bfloat16 h1 = __float2bfloat16_rn(v.y);
    __nv_bfloat16 h2 = __float2bfloat16_rn(v.z);
    __nv_bfloat16 h3 = __float2bfloat16_rn(v.w);
    ((__nv_bfloat162*)(dH + i4))[0] = __halves2bfloat162(h0, h1);
    ((__nv_bfloat162*)(dH + i4))[1] = __halves2bfloat162(h2, h3);
    ((__nv_bfloat162*)(dL + i4))[0] = __halves2bfloat162(
        __float2bfloat16_rn(v.x - __bfloat162float(h0)),
        __float2bfloat16_rn(v.y - __bfloat162float(h1)));
    ((__nv_bfloat162*)(dL + i4))[1] = __halves2bfloat162(
        __float2bfloat16_rn(v.z - __bfloat162float(h2)),
        __float2bfloat16_rn(v.w - __bfloat162float(h3)));
}

// ---------------------------------------------------------------------------
// 3xBF16 NT GEMM (R8 version: scalar LDS frag loads — LDSM was slower).
// BM=128, BN=64, BK=32, 256 threads = 8 warps (4m x 2n), warp tile 32x32.
// ---------------------------------------------------------------------------
#define A_STG (128 * 40)
#define B_STG (64 * 40)
#define U_AH 0
#define U_AL (2 * A_STG)
#define U_BH (4 * A_STG)
#define U_BL (4 * A_STG + 2 * B_STG)
#define GEMM_SMEM ((4 * A_STG + 4 * B_STG) * 2)   // 61440 bytes

__device__ __forceinline__ void scat_qkv(int m, int n, float v0, float v1) {
    int b = m >> 11;
    int t = m & 2047;
    int which = n / NC;
    int r = n - which * NC;
    int h = r >> 6;
    int d = r & 63;
    float* dst = (which == 0) ? g_q : (which == 1) ? g_k : g_v;
    *(float2*)(dst + (((size_t)b * NH + h) * NT + t) * ND + d) = make_float2(v0, v1);
}

template<int MODE>
__global__ void __launch_bounds__(256, 2)
gemm3bf(float* __restrict__ Cout, int K, int N)
{
    extern __shared__ __align__(16) unsigned short us[];

    const __nv_bfloat16* AH = (MODE == 0) ? g_xH  : g_yH;
    const __nv_bfloat16* AL = (MODE == 0) ? g_xL  : g_yL;
    const __nv_bfloat16* BH = (MODE == 0) ? g_waH : g_wpH;
    const __nv_bfloat16* BL = (MODE == 0) ? g_waL : g_wpL;

    const uint32_t sb = smem_to_u32(us);
    const int m0 = blockIdx.y * 128;
    const int n0 = blockIdx.x * 64;
    const int tid = threadIdx.x;
    const int wid = tid >> 5, lane = tid & 31;
    const int g = lane >> 2, t = lane & 3;
    const int wm = wid >> 1, wn = wid & 1;

    const int arow0 = tid >> 2;
    const int ac8   = (tid & 3) * 8;
    const int brow  = tid >> 2;
    const int bc8   = (tid & 3) * 8;

    auto load_stage = [&](int s, int k0) {
        #pragma unroll
        for (int i = 0; i < 2; i++) {
            int row = arow0 + i * 64;
            uint32_t so = (uint32_t)(row * 40 + ac8) * 2;
            size_t ga = (size_t)(m0 + row) * K + k0 + ac8;
            cp_async16(sb + (U_AH + s * A_STG) * 2 + so, AH + ga);
            cp_async16(sb + (U_AL + s * A_STG) * 2 + so, AL + ga);
        }
        {
            uint32_t so = (uint32_t)(brow * 40 + bc8) * 2;
            size_t gb = (size_t)(n0 + brow) * K + k0 + bc8;
            cp_async16(sb + (U_BH + s * B_STG) * 2 + so, BH + gb);
            cp_async16(sb + (U_BL + s * B_STG) * 2 + so, BL + gb);
        }
        cp_commit();
    };

    float acc[2][4][4];
    #pragma unroll
    for (int mt = 0; mt < 2; mt++)
        #pragma unroll
        for (int nt = 0; nt < 4; nt++)
            #pragma unroll
            for (int i = 0; i < 4; i++) acc[mt][nt][i] = 0.0f;

    const int NK = K / 32;
    load_stage(0, 0);

    for (int c = 0; c < NK; c++) {
        cp_wait0();
        __syncthreads();
        if (c + 1 < NK) load_stage((c + 1) & 1, (c + 1) * 32);

        const unsigned short* sAH = us + U_AH + (c & 1) * A_STG;
        const unsigned short* sAL = us + U_AL + (c & 1) * A_STG;
        const unsigned short* sBH = us + U_BH + (c & 1) * B_STG;
        const unsigned short* sBL = us + U_BL + (c & 1) * B_STG;

        #pragma unroll
        for (int ks = 0; ks < 2; ks++) {
            const int ko = ks * 16;
            unsigned aH[2][4], aL[2][4], bH[4][2], bL[4][2];
            #pragma unroll
            for (int mt = 0; mt < 2; mt++) {
                int r = wm * 32 + mt * 16 + g;
                int b0o = r * 40 + ko + 2 * t;
                int b1o = (r + 8) * 40 + ko + 2 * t;
                aH[mt][0] = *(const unsigned*)(sAH + b0o);
                aH[mt][1] = *(const unsigned*)(sAH + b1o);
                aH[mt][2] = *(const unsigned*)(sAH + b0o + 8);
                aH[mt][3] = *(const unsigned*)(sAH + b1o + 8);
                aL[mt][0] = *(const unsigned*)(sAL + b0o);
                aL[mt][1] = *(const unsigned*)(sAL + b1o);
                aL[mt][2] = *(const unsigned*)(sAL + b0o + 8);
                aL[mt][3] = *(const unsigned*)(sAL + b1o + 8);
            }
            #pragma unroll
            for (int nt = 0; nt < 4; nt++) {
                int r = wn * 32 + nt * 8 + g;
                int bo = r * 40 + ko + 2 * t;
                bH[nt][0] = *(const unsigned*)(sBH + bo);
                bH[nt][1] = *(const unsigned*)(sBH + bo + 8);
                bL[nt][0] = *(const unsigned*)(sBL + bo);
                bL[nt][1] = *(const unsigned*)(sBL + bo + 8);
            }
            #pragma unroll
            for (int mt = 0; mt < 2; mt++)
                #pragma unroll
                for (int nt = 0; nt < 4; nt++) {
                    mma_bf16(acc[mt][nt], aH[mt], bH[nt][0], bH[nt][1]);
                    mma_bf16(acc[mt][nt], aH[mt], bL[nt][0], bL[nt][1]);
                    mma_bf16(acc[mt][nt], aL[mt], bH[nt][0], bH[nt][1]);
                }
        }
        __syncthreads();
    }

    #pragma unroll
    for (int mt = 0; mt < 2; mt++) {
        int r0 = m0 + wm * 32 + mt * 16 + g;
        int r1 = r0 + 8;
        #pragma unroll
        for (int nt = 0; nt < 4; nt++) {
            int c = n0 + wn * 32 + nt * 8 + 2 * t;
            if (MODE == 0) {
                scat_qkv(r0, c, acc[mt][nt][0], acc[mt][nt][1]);
                scat_qkv(r1, c, acc[mt][nt][2], acc[mt][nt][3]);
            } else {
                *(float2*)(Cout + (size_t)r0 * N + c) =
                    make_float2(acc[mt][nt][0], acc[mt][nt][1]);
                *(float2*)(Cout + (size_t)r1 * N + c) =
                    make_float2(acc[mt][nt][2], acc[mt][nt][3]);
            }
        }
    }
}

// ---------------------------------------------------------------------------
// Flash attention, tf32 mma.sync.
// Q in smem (rna tf32, persistent). K/V cp.async double-buffered (raw fp32 ->
// tf32 truncation in MMA). P never touches smem: the S->A-fragment relayout is
// an intra-quad shuffle. One __syncthreads per K-tile.
// smem u32: [Q 128x68][stage0: K 64x68 | V 64x72][stage1: same]
// ---------------------------------------------------------------------------
#define AQ_U   (128 * 68)
#define AKV_K  0
#define AKV_V  (64 * 68)
#define AKV_STG (64 * 68 + 64 * 72)     // 8960 u32 per stage
#define ATTN_U (AQ_U + 2 * AKV_STG)     // 26624 u32
#define ATTN_SMEM (ATTN_U * 4)          // 106496 bytes -> 2 CTAs/SM

__global__ void __launch_bounds__(256, 2) attn_mma()
{
    extern __shared__ __align__(16) unsigned su[];
    const uint32_t sb = smem_to_u32(su);
    unsigned* Qs = su;

    const int qt = (int)gridDim.x - 1 - (int)blockIdx.x;   // heavy blocks first
    const int bh = blockIdx.y;
    const int b = bh / NH;
    const int h = bh - b * NH;
    const int tid = threadIdx.x;
    const int wid = tid >> 5, lane = tid & 31;
    const int g = lane >> 2, t = lane & 3;
    const int R = wid * 16;
    const int odd = t & 1;
    const int srcA = (lane & ~3) | (t >> 1);
    const int srcB = srcA + 2;

    const size_t head_base = ((size_t)b * NH + h) * (size_t)NT * ND;
    const int q0 = qt * 128;

    // ---- load Q tile (rna tf32, persistent in smem) ----
    {
        const float* qg = g_q + head_base + (size_t)q0 * ND;
        #pragma unroll
        for (int i = 0; i < 8; i++) {
            int idx = tid + i * 256;
            int row = idx >> 4, d4 = (idx & 15) << 2;
            float4 v = *(const float4*)(qg + row * ND + d4);
            *(uint4*)(Qs + row * 68 + d4) =
                make_uint4(f2tf32(v.x), f2tf32(v.y), f2tf32(v.z), f2tf32(v.w));
        }
    }

    const int kt_max = 2 * qt + 1;

    auto issue_kv = [&](int s, int k0) {
        const float* kg = g_k + head_base + (size_t)k0 * ND;
        const float* vg = g_v + head_base + (size_t)k0 * ND;
        #pragma unroll
        for (int i = 0; i < 4; i++) {
            int idx = tid + i * 256;
            int row = idx >> 4, c4 = (idx & 15) << 2;
            cp_async16(sb + (uint32_t)(AQ_U + s * AKV_STG + AKV_K + row * 68 + c4) * 4,
                       kg + row * ND + c4);
            cp_async16(sb + (uint32_t)(AQ_U + s * AKV_STG + AKV_V + row * 72 + c4) * 4,
                       vg + row * ND + c4);
        }
        cp_commit();
    };

    issue_kv(0, 0);

    float mrow[2] = {-1e30f, -1e30f};
    float lrow[2] = {0.0f, 0.0f};
    float o[8][4];
    #pragma unroll
    for (int nt = 0; nt < 8; nt++)
        #pragma unroll
        for (int i = 0; i < 4; i++) o[nt][i] = 0.0f;

    for (int kt = 0; kt <= kt_max; kt++) {
        cp_wait0();
        __syncthreads();   // stage kt landed; Q visible (iter 0); prev readers done
        if (kt + 1 <= kt_max) issue_kv((kt + 1) & 1, (kt + 1) * 64);

        const unsigned* Ks = su + AQ_U + (kt & 1) * AKV_STG + AKV_K;
        const unsigned* Vs = su + AQ_U + (kt & 1) * AKV_STG + AKV_V;
        const int k0 = kt * 64;

        // ---- S = Q K^T ----
        float sc[8][4];
        #pragma unroll
        for (int nt = 0; nt < 8; nt++)
            #pragma unroll
            for (int i = 0; i < 4; i++) sc[nt][i] = 0.0f;

        #pragma unroll
        for (int ks = 0; ks < 8; ks++) {
            unsigned a[4];
            int ra = (R + g) * 68 + ks * 8 + t;
            int rb = (R + g + 8) * 68 + ks * 8 + t;
            a[0] = Qs[ra]; a[1] = Qs[rb]; a[2] = Qs[ra + 4]; a[3] = Qs[rb + 4];
            #pragma unroll
            for (int nt = 0; nt < 8; nt++) {
                int kb = (nt * 8 + g) * 68 + ks * 8 + t;
                mma_tf32(sc[nt], a, Ks[kb], Ks[kb + 4]);
            }
        }

        // ---- scale + causal mask ----
        const bool nm = (kt >= 2 * qt);
        const int rlo = q0 + R + g;
        const int rhi = rlo + 8;
        #pragma unroll
        for (int nt = 0; nt < 8; nt++) {
            int cc = k0 + nt * 8 + 2 * t;
            sc[nt][0] *= 0.125f; sc[nt][1] *= 0.125f;
            sc[nt][2] *= 0.125f; sc[nt][3] *= 0.125f;
            if (nm) {
                if (cc > rlo)     sc[nt][0] = -1e30f;
                if (cc + 1 > rlo) sc[nt][1] = -1e30f;
                if (cc > rhi)     sc[nt][2] = -1e30f;
                if (cc + 1 > rhi) sc[nt][3] = -1e30f;
            }
        }

        // ---- online softmax ----
        float mx0 = -1e30f, mx1 = -1e30f;
        #pragma unroll
        for (int nt = 0; nt < 8; nt++) {
            mx0 = fmaxf(mx0, fmaxf(sc[nt][0], sc[nt][1]));
            mx1 = fmaxf(mx1, fmaxf(sc[nt][2], sc[nt][3]));
        }
        mx0 = fmaxf(mx0, __shfl_xor_sync(0xffffffffu, mx0, 1));
        mx0 = fmaxf(mx0, __shfl_xor_sync(0xffffffffu, mx0, 2));
        mx1 = fmaxf(mx1, __shfl_xor_sync(0xffffffffu, mx1, 1));
        mx1 = fmaxf(mx1, __shfl_xor_sync(0xffffffffu, mx1, 2));

        float mn0 = fmaxf(mrow[0], mx0);
        float mn1 = fmaxf(mrow[1], mx1);
        float al0 = __expf(mrow[0] - mn0);
        float al1 = __expf(mrow[1] - mn1);
        mrow[0] = mn0; mrow[1] = mn1;

        float rs0 = 0.0f, rs1 = 0.0f;
        #pragma unroll
        for (int nt = 0; nt < 8; nt++) {
            sc[nt][0] = __expf(sc[nt][0] - mn0); rs0 += sc[nt][0];
            sc[nt][1] = __expf(sc[nt][1] - mn0); rs0 += sc[nt][1];
            sc[nt][2] = __expf(sc[nt][2] - mn1); rs1 += sc[nt][2];
            sc[nt][3] = __expf(sc[nt][3] - mn1); rs1 += sc[nt][3];
        }
        rs0 += __shfl_xor_sync(0xffffffffu, rs0, 1);
        rs0 += __shfl_xor_sync(0xffffffffu, rs0, 2);
        rs1 += __shfl_xor_sync(0xffffffffu, rs1, 1);
        rs1 += __shfl_xor_sync(0xffffffffu, rs1, 2);
        lrow[0] = lrow[0] * al0 + rs0;
        lrow[1] = lrow[1] * al1 + rs1;

        #pragma unroll
        for (int nt = 0; nt < 8; nt++) {
            o[nt][0] *= al0; o[nt][1] *= al0;
            o[nt][2] *= al1; o[nt][3] *= al1;
        }

        // ---- O += P V : P A-fragments via intra-quad shuffle (no smem) ----
        // lane(g,t) needs P[g][8ks+t], P[g+8][8ks+t] (from lane srcA) and the
        // +4 columns (from lane srcB); sc[ks][t&1 / 2+(t&1)] of the source lane.
        #pragma unroll
        for (int ks = 0; ks < 8; ks++) {
            unsigned p0 = f2tf32(sc[ks][0]);
            unsigned p1 = f2tf32(sc[ks][1]);
            unsigned p2 = f2tf32(sc[ks][2]);
            unsigned p3 = f2tf32(sc[ks][3]);
            unsigned u0 = __shfl_sync(0xffffffffu, p0, srcA);
            unsigned u1 = __shfl_sync(0xffffffffu, p1, srcA);
            unsigned u2 = __shfl_sync(0xffffffffu, p2, srcA);
            unsigned u3 = __shfl_sync(0xffffffffu, p3, srcA);
            unsigned w0 = __shfl_sync(0xffffffffu, p0, srcB);
            unsigned w1 = __shfl_sync(0xffffffffu, p1, srcB);
            unsigned w2 = __shfl_sync(0xffffffffu, p2, srcB);
            unsigned w3 = __shfl_sync(0xffffffffu, p3, srcB);
            unsigned a[4];
            a[0] = odd ? u1 : u0;
            a[1] = odd ? u3 : u2;
            a[2] = odd ? w1 : w0;
            a[3] = odd ? w3 : w2;
            #pragma unroll
            for (int nt = 0; nt < 8; nt++) {
                int v0 = (ks * 8 + t) * 72 + nt * 8 + g;
                int v1 = (ks * 8 + t + 4) * 72 + nt * 8 + g;
                mma_tf32(o[nt], a, Vs[v0], Vs[v1]);
            }
        }
    }

    // ---- epilogue: normalize; emit bf16 hi/lo for the proj GEMM ----
    float i0 = 1.0f / lrow[0];
    float i1 = 1.0f / lrow[1];
    size_t base0 = ((size_t)b * NT + (q0 + R + g)) * NC + h * ND;
    size_t base1 = ((size_t)b * NT + (q0 + R + g + 8)) * NC + h * ND;
    #pragma unroll
    for (int nt = 0; nt < 8; nt++) {
        size_t off0 = base0 + nt * 8 + 2 * t;
        size_t off1 = base1 + nt * 8 + 2 * t;
        float v0 = o[nt][0] * i0, v1 = o[nt][1] * i0;
        float v2 = o[nt][2] * i1, v3 = o[nt][3] * i1;
        __nv_bfloat16 h0 = __float2bfloat16_rn(v0);
        __nv_bfloat16 h1 = __float2bfloat16_rn(v1);
        __nv_bfloat16 h2 = __float2bfloat16_rn(v2);
        __nv_bfloat16 h3 = __float2bfloat16_rn(v3);
        *(__nv_bfloat162*)(g_yH + off0) = __halves2bfloat162(h0, h1);
        *(__nv_bfloat162*)(g_yH + off1) = __halves2bfloat162(h2, h3);
        *(__nv_bfloat162*)(g_yL + off0) = __halves2bfloat162(
            __float2bfloat16_rn(v0 - __bfloat162float(h0)),
            __float2bfloat16_rn(v1 - __bfloat162float(h1)));
        *(__nv_bfloat162*)(g_yL + off1) = __halves2bfloat162(
            __float2bfloat16_rn(v2 - __bfloat162float(h2)),
            __float2bfloat16_rn(v3 - __bfloat162float(h3)));
    }
}

// ---------------------------------------------------------------------------
extern "C" void kernel_launch(void* const* d_in, const int* in_sizes, int n_in,
                              void* d_out, int out_size)
{
    const float* x  = nullptr;   // 3145728
    const float* Wa = nullptr;   // 1769472
    const float* Wp = nullptr;   // 589824
    for (int i = 0; i < n_in; i++) {
        if (in_sizes[i] == NB * NT * NC)      x  = (const float*)d_in[i];
        else if (in_sizes[i] == 3 * NC * NC)  Wa = (const float*)d_in[i];
        else if (in_sizes[i] == NC * NC)      Wp = (const float*)d_in[i];
    }
    float* out = (float*)d_out;

    cudaFuncSetAttribute(attn_mma,
                         cudaFuncAttributeMaxDynamicSharedMemorySize, ATTN_SMEM);
    cudaFuncSetAttribute(gemm3bf<0>,
                         cudaFuncAttributeMaxDynamicSharedMemorySize, GEMM_SMEM);
    cudaFuncSetAttribute(gemm3bf<1>,
                         cudaFuncAttributeMaxDynamicSharedMemorySize, GEMM_SMEM);

    // 0) one-time hi/lo bf16 splits
    split_bf<<<(NB * NT * NC) / 1024, 256>>>(x, 0);
    split_bf<<<(3 * NC * NC) / 1024, 256>>>(Wa, 1);
    split_bf<<<(NC * NC) / 1024, 256>>>(Wp, 2);

    // 1) QKV projection, scatter q/k/v
    gemm3bf<0><<<dim3(3 * NC / 64, NB * NT / 128), 256, GEMM_SMEM>>>(nullptr, NC, 3 * NC);

    // 2) causal flash attention -> yH/yL bf16
    attn_mma<<<dim3(NT / 128, NB * NH), 256, ATTN_SMEM>>>();

    // 3) output projection
    gemm3bf<1><<<dim3(NC / 64, NB * NT / 128), 256, GEMM_SMEM>>>(out, NC, NC);
}

// round 13
// speedup vs baseline: 1.6748x; 1.1412x over previous
#include <cuda_runtime.h>
#include <cuda_bf16.h>
#include <math.h>
#include <stdint.h>

#define NB 2
#define NT 2048
#define NC 768
#define NH 12
#define ND 64

// ---------------------------------------------------------------------------
// Device-global scratch (allocation-free rule). All tensor operands are kept
// pre-rounded to tf32 (rna) so tf32 mma truncation is exact & unbiased.
// ---------------------------------------------------------------------------
__device__ float g_q[NB*NH*NT*ND];     // [b][h][t][d], rna-tf32 fp32
__device__ float g_k[NB*NH*NT*ND];
__device__ float g_v[NB*NH*NT*ND];
__device__ float g_y[NB*NT*NC];        // attention out, rna-tf32 fp32
__device__ __align__(16) float g_x32[NB*NT*NC];   // rounded inputs
__device__ __align__(16) float g_wa32[3*NC*NC];
__device__ __align__(16) float g_wp32[NC*NC];

// ---------------------------------------------------------------------------
// helpers
// ---------------------------------------------------------------------------
__device__ __forceinline__ uint32_t smem_to_u32(const void* p) {
    uint32_t a;
    asm("{ .reg .u64 t; cvta.to.shared.u64 t, %1; cvt.u32.u64 %0, t; }"
        : "=r"(a) : "l"(p));
    return a;
}

__device__ __forceinline__ void cp_async16(uint32_t saddr, const void* gptr) {
    asm volatile("cp.async.cg.shared.global [%0], [%1], 16;"
                 :: "r"(saddr), "l"(gptr) : "memory");
}
__device__ __forceinline__ void cp_commit() {
    asm volatile("cp.async.commit_group;" ::: "memory");
}
__device__ __forceinline__ void cp_wait0() {
    asm volatile("cp.async.wait_group 0;" ::: "memory");
}

__device__ __forceinline__ unsigned f2tf32(float x) {
    unsigned r;
    asm("cvt.rna.tf32.f32 %0, %1;" : "=r"(r) : "f"(x));
    return r;
}
__device__ __forceinline__ float rnd_tf32(float x) {
    return __uint_as_float(f2tf32(x));
}

// D += A*B, m16n8k8 tf32
__device__ __forceinline__ void mma_tf32(float c[4], const unsigned a[4],
                                         unsigned b0, unsigned b1) {
    asm volatile(
        "mma.sync.aligned.m16n8k8.row.col.f32.tf32.tf32.f32 "
        "{%0,%1,%2,%3},{%4,%5,%6,%7},{%8,%9},{%0,%1,%2,%3};\n"
        : "+f"(c[0]), "+f"(c[1]), "+f"(c[2]), "+f"(c[3])
        : "r"(a[0]), "r"(a[1]), "r"(a[2]), "r"(a[3]), "r"(b0), "r"(b1));
}

// ---------------------------------------------------------------------------
// Round fp32 -> rna-tf32 fp32 (elementwise), 4 elems/thread
// ---------------------------------------------------------------------------
__global__ void round_tf32(const float* __restrict__ s, float* __restrict__ d) {
    int i4 = (blockIdx.x * 256 + threadIdx.x) * 4;
    float4 v = *(const float4*)(s + i4);
    v.x = rnd_tf32(v.x); v.y = rnd_tf32(v.y);
    v.z = rnd_tf32(v.z); v.w = rnd_tf32(v.w);
    *(float4*)(d + i4) = v;
}

// ---------------------------------------------------------------------------
// Single-pass TF32 NT GEMM: C[m,n] = sum_k A[m,k]*B[n,k] (operands rna-tf32).
// BM=128, BN=64, BK=32, 256 threads = 8 warps (4m x 2n), warp tile 32x32.
// cp.async double-buffered. smem fp32, row stride 36 (conflict-free: 4g+t).
// MODE 0: scatter (rounded) -> g_q/g_k/g_v    MODE 1: row-major -> Cout
// ---------------------------------------------------------------------------
#define TA_STG (128 * 36)
#define TB_STG (64 * 36)
#define TU_A 0
#define TU_B (2 * TA_STG)
#define GEMM_SMEM ((2 * TA_STG + 2 * TB_STG) * 4)   // 55296 bytes

__device__ __forceinline__ void scat_qkv(int m, int n, float v0, float v1) {
    int b = m >> 11;
    int t = m & 2047;
    int which = n / NC;
    int r = n - which * NC;
    int h = r >> 6;
    int d = r & 63;
    float* dst = (which == 0) ? g_q : (which == 1) ? g_k : g_v;
    *(float2*)(dst + (((size_t)b * NH + h) * NT + t) * ND + d) =
        make_float2(rnd_tf32(v0), rnd_tf32(v1));
}

template<int MODE>
__global__ void __launch_bounds__(256, 2)
gemm_tf(float* __restrict__ Cout, int K, int N)
{
    extern __shared__ __align__(16) float fs[];

    const float* Ag = (MODE == 0) ? g_x32  : g_y;
    const float* Bg = (MODE == 0) ? g_wa32 : g_wp32;

    const uint32_t sb = smem_to_u32(fs);
    const int m0 = blockIdx.y * 128;
    const int n0 = blockIdx.x * 64;
    const int tid = threadIdx.x;
    const int wid = tid >> 5, lane = tid & 31;
    const int g = lane >> 2, t = lane & 3;
    const int wm = wid >> 1, wn = wid & 1;

    auto load_stage = [&](int s, int k0) {
        // A: 128x32 fp32 = 1024 float4 (4/thread)
        #pragma unroll
        for (int i = 0; i < 4; i++) {
            int idx = tid + i * 256;
            int row = idx >> 3, c4 = (idx & 7) * 4;
            cp_async16(sb + (uint32_t)(TU_A + s * TA_STG + row * 36 + c4) * 4,
                       Ag + (size_t)(m0 + row) * K + k0 + c4);
        }
        // B: 64x32 fp32 = 512 float4 (2/thread)
        #pragma unroll
        for (int i = 0; i < 2; i++) {
            int idx = tid + i * 256;
            int row = idx >> 3, c4 = (idx & 7) * 4;
            cp_async16(sb + (uint32_t)(TU_B + s * TB_STG + row * 36 + c4) * 4,
                       Bg + (size_t)(n0 + row) * K + k0 + c4);
        }
        cp_commit();
    };

    float acc[2][4][4];
    #pragma unroll
    for (int mt = 0; mt < 2; mt++)
        #pragma unroll
        for (int nt = 0; nt < 4; nt++)
            #pragma unroll
            for (int i = 0; i < 4; i++) acc[mt][nt][i] = 0.0f;

    const int NK = K / 32;
    load_stage(0, 0);

    for (int c = 0; c < NK; c++) {
        cp_wait0();
        __syncthreads();
        if (c + 1 < NK) load_stage((c + 1) & 1, (c + 1) * 32);

        const unsigned* As = (const unsigned*)fs + TU_A + (c & 1) * TA_STG;
        const unsigned* Bs = (const unsigned*)fs + TU_B + (c & 1) * TB_STG;

        #pragma unroll
        for (int ks = 0; ks < 4; ks++) {
            const int ko = ks * 8;
            unsigned a[2][4], b[4][2];
            #pragma unroll
            for (int mt = 0; mt < 2; mt++) {
                int base = (wm * 32 + mt * 16 + g) * 36 + ko + t;
                a[mt][0] = As[base];
                a[mt][1] = As[base + 8 * 36];
                a[mt][2] = As[base + 4];
                a[mt][3] = As[base + 8 * 36 + 4];
            }
            #pragma unroll
            for (int nt = 0; nt < 4; nt++) {
                int bb = (wn * 32 + nt * 8 + g) * 36 + ko + t;
                b[nt][0] = Bs[bb];
                b[nt][1] = Bs[bb + 4];
            }
            #pragma unroll
            for (int mt = 0; mt < 2; mt++)
                #pragma unroll
                for (int nt = 0; nt < 4; nt++)
                    mma_tf32(acc[mt][nt], a[mt], b[nt][0], b[nt][1]);
        }
        __syncthreads();
    }

    #pragma unroll
    for (int mt = 0; mt < 2; mt++) {
        int r0 = m0 + wm * 32 + mt * 16 + g;
        int r1 = r0 + 8;
        #pragma unroll
        for (int nt = 0; nt < 4; nt++) {
            int c = n0 + wn * 32 + nt * 8 + 2 * t;
            if (MODE == 0) {
                scat_qkv(r0, c, acc[mt][nt][0], acc[mt][nt][1]);
                scat_qkv(r1, c, acc[mt][nt][2], acc[mt][nt][3]);
            } else {
                *(float2*)(Cout + (size_t)r0 * N + c) =
                    make_float2(acc[mt][nt][0], acc[mt][nt][1]);
                *(float2*)(Cout + (size_t)r1 * N + c) =
                    make_float2(acc[mt][nt][2], acc[mt][nt][3]);
            }
        }
    }
}

// ---------------------------------------------------------------------------
// Flash attention, tf32 mma.sync (structure identical to R10 / 381us kernel).
// Q in smem (tf32, persistent). K/V cp.async double-buffered (pre-rounded ->
// truncation exact). P relayout via intra-quad shuffle. Epilogue -> g_y fp32.
// smem u32: [Q 128x68][stage0: K 64x68 | V 64x72][stage1: same]
// ---------------------------------------------------------------------------
#define AQ_U   (128 * 68)
#define AKV_K  0
#define AKV_V  (64 * 68)
#define AKV_STG (64 * 68 + 64 * 72)     // 8960 u32 per stage
#define ATTN_U (AQ_U + 2 * AKV_STG)     // 26624 u32
#define ATTN_SMEM (ATTN_U * 4)          // 106496 bytes -> 2 CTAs/SM

__global__ void __launch_bounds__(256, 2) attn_mma()
{
    extern __shared__ __align__(16) unsigned su[];
    const uint32_t sb = smem_to_u32(su);
    unsigned* Qs = su;

    const int qt = (int)gridDim.x - 1 - (int)blockIdx.x;   // heavy blocks first
    const int bh = blockIdx.y;
    const int b = bh / NH;
    const int h = bh - b * NH;
    const int tid = threadIdx.x;
    const int wid = tid >> 5, lane = tid & 31;
    const int g = lane >> 2, t = lane & 3;
    const int R = wid * 16;
    const int odd = t & 1;
    const int srcA = (lane & ~3) | (t >> 1);
    const int srcB = srcA + 2;

    const size_t head_base = ((size_t)b * NH + h) * (size_t)NT * ND;
    const int q0 = qt * 128;

    // ---- load Q tile (already rounded; copy bits) ----
    {
        const float* qg = g_q + head_base + (size_t)q0 * ND;
        #pragma unroll
        for (int i = 0; i < 8; i++) {
            int idx = tid + i * 256;
            int row = idx >> 4, d4 = (idx & 15) << 2;
            *(uint4*)(Qs + row * 68 + d4) = *(const uint4*)(qg + row * ND + d4);
        }
    }

    const int kt_max = 2 * qt + 1;

    auto issue_kv = [&](int s, int k0) {
        const float* kg = g_k + head_base + (size_t)k0 * ND;
        const float* vg = g_v + head_base + (size_t)k0 * ND;
        #pragma unroll
        for (int i = 0; i < 4; i++) {
            int idx = tid + i * 256;
            int row = idx >> 4, c4 = (idx & 15) << 2;
            cp_async16(sb + (uint32_t)(AQ_U + s * AKV_STG + AKV_K + row * 68 + c4) * 4,
                       kg + row * ND + c4);
            cp_async16(sb + (uint32_t)(AQ_U + s * AKV_STG + AKV_V + row * 72 + c4) * 4,
                       vg + row * ND + c4);
        }
        cp_commit();
    };

    issue_kv(0, 0);

    float mrow[2] = {-1e30f, -1e30f};
    float lrow[2] = {0.0f, 0.0f};
    float o[8][4];
    #pragma unroll
    for (int nt = 0; nt < 8; nt++)
        #pragma unroll
        for (int i = 0; i < 4; i++) o[nt][i] = 0.0f;

    for (int kt = 0; kt <= kt_max; kt++) {
        cp_wait0();
        __syncthreads();   // stage kt landed; Q visible (iter 0); prev readers done
        if (kt + 1 <= kt_max) issue_kv((kt + 1) & 1, (kt + 1) * 64);

        const unsigned* Ks = su + AQ_U + (kt & 1) * AKV_STG + AKV_K;
        const unsigned* Vs = su + AQ_U + (kt & 1) * AKV_STG + AKV_V;
        const int k0 = kt * 64;

        // ---- S = Q K^T ----
        float sc[8][4];
        #pragma unroll
        for (int nt = 0; nt < 8; nt++)
            #pragma unroll
            for (int i = 0; i < 4; i++) sc[nt][i] = 0.0f;

        #pragma unroll
        for (int ks = 0; ks < 8; ks++) {
            unsigned a[4];
            int ra = (R + g) * 68 + ks * 8 + t;
            int rb = (R + g + 8) * 68 + ks * 8 + t;
            a[0] = Qs[ra]; a[1] = Qs[rb]; a[2] = Qs[ra + 4]; a[3] = Qs[rb + 4];
            #pragma unroll
            for (int nt = 0; nt < 8; nt++) {
                int kb = (nt * 8 + g) * 68 + ks * 8 + t;
                mma_tf32(sc[nt], a, Ks[kb], Ks[kb + 4]);
            }
        }

        // ---- scale + causal mask ----
        const bool nm = (kt >= 2 * qt);
        const int rlo = q0 + R + g;
        const int rhi = rlo + 8;
        #pragma unroll
        for (int nt = 0; nt < 8; nt++) {
            int cc = k0 + nt * 8 + 2 * t;
            sc[nt][0] *= 0.125f; sc[nt][1] *= 0.125f;
            sc[nt][2] *= 0.125f; sc[nt][3] *= 0.125f;
            if (nm) {
                if (cc > rlo)     sc[nt][0] = -1e30f;
                if (cc + 1 > rlo) sc[nt][1] = -1e30f;
                if (cc > rhi)     sc[nt][2] = -1e30f;
                if (cc + 1 > rhi) sc[nt][3] = -1e30f;
            }
        }

        // ---- online softmax ----
        float mx0 = -1e30f, mx1 = -1e30f;
        #pragma unroll
        for (int nt = 0; nt < 8; nt++) {
            mx0 = fmaxf(mx0, fmaxf(sc[nt][0], sc[nt][1]));
            mx1 = fmaxf(mx1, fmaxf(sc[nt][2], sc[nt][3]));
        }
        mx0 = fmaxf(mx0, __shfl_xor_sync(0xffffffffu, mx0, 1));
        mx0 = fmaxf(mx0, __shfl_xor_sync(0xffffffffu, mx0, 2));
        mx1 = fmaxf(mx1, __shfl_xor_sync(0xffffffffu, mx1, 1));
        mx1 = fmaxf(mx1, __shfl_xor_sync(0xffffffffu, mx1, 2));

        float mn0 = fmaxf(mrow[0], mx0);
        float mn1 = fmaxf(mrow[1], mx1);
        float al0 = __expf(mrow[0] - mn0);
        float al1 = __expf(mrow[1] - mn1);
        mrow[0] = mn0; mrow[1] = mn1;

        float rs0 = 0.0f, rs1 = 0.0f;
        #pragma unroll
        for (int nt = 0; nt < 8; nt++) {
            sc[nt][0] = __expf(sc[nt][0] - mn0); rs0 += sc[nt][0];
            sc[nt][1] = __expf(sc[nt][1] - mn0); rs0 += sc[nt][1];
            sc[nt][2] = __expf(sc[nt][2] - mn1); rs1 += sc[nt][2];
            sc[nt][3] = __expf(sc[nt][3] - mn1); rs1 += sc[nt][3];
        }
        rs0 += __shfl_xor_sync(0xffffffffu, rs0, 1);
        rs0 += __shfl_xor_sync(0xffffffffu, rs0, 2);
        rs1 += __shfl_xor_sync(0xffffffffu, rs1, 1);
        rs1 += __shfl_xor_sync(0xffffffffu, rs1, 2);
        lrow[0] = lrow[0] * al0 + rs0;
        lrow[1] = lrow[1] * al1 + rs1;

        #pragma unroll
        for (int nt = 0; nt < 8; nt++) {
            o[nt][0] *= al0; o[nt][1] *= al0;
            o[nt][2] *= al1; o[nt][3] *= al1;
        }

        // ---- O += P V : P A-fragments via intra-quad shuffle (no smem) ----
        #pragma unroll
        for (int ks = 0; ks < 8; ks++) {
            unsigned p0 = f2tf32(sc[ks][0]);
            unsigned p1 = f2tf32(sc[ks][1]);
            unsigned p2 = f2tf32(sc[ks][2]);
            unsigned p3 = f2tf32(sc[ks][3]);
            unsigned u0 = __shfl_sync(0xffffffffu, p0, srcA);
            unsigned u1 = __shfl_sync(0xffffffffu, p1, srcA);
            unsigned u2 = __shfl_sync(0xffffffffu, p2, srcA);
            unsigned u3 = __shfl_sync(0xffffffffu, p3, srcA);
            unsigned w0 = __shfl_sync(0xffffffffu, p0, srcB);
            unsigned w1 = __shfl_sync(0xffffffffu, p1, srcB);
            unsigned w2 = __shfl_sync(0xffffffffu, p2, srcB);
            unsigned w3 = __shfl_sync(0xffffffffu, p3, srcB);
            unsigned a[4];
            a[0] = odd ? u1 : u0;
            a[1] = odd ? u3 : u2;
            a[2] = odd ? w1 : w0;
            a[3] = odd ? w3 : w2;
            #pragma unroll
            for (int nt = 0; nt < 8; nt++) {
                int v0 = (ks * 8 + t) * 72 + nt * 8 + g;
                int v1 = (ks * 8 + t + 4) * 72 + nt * 8 + g;
                mma_tf32(o[nt], a, Vs[v0], Vs[v1]);
            }
        }
    }

    // ---- epilogue: normalize; write rounded fp32 y for the proj GEMM ----
    float i0 = 1.0f / lrow[0];
    float i1 = 1.0f / lrow[1];
    size_t base0 = ((size_t)b * NT + (q0 + R + g)) * NC + h * ND;
    size_t base1 = ((size_t)b * NT + (q0 + R + g + 8)) * NC + h * ND;
    #pragma unroll
    for (int nt = 0; nt < 8; nt++) {
        size_t off0 = base0 + nt * 8 + 2 * t;
        size_t off1 = base1 + nt * 8 + 2 * t;
        *(float2*)(g_y + off0) = make_float2(rnd_tf32(o[nt][0] * i0),
                                             rnd_tf32(o[nt][1] * i0));
        *(float2*)(g_y + off1) = make_float2(rnd_tf32(o[nt][2] * i1),
                                             rnd_tf32(o[nt][3] * i1));
    }
}

// ---------------------------------------------------------------------------
extern "C" void kernel_launch(void* const* d_in, const int* in_sizes, int n_in,
                              void* d_out, int out_size)
{
    const float* x  = nullptr;   // 3145728
    const float* Wa = nullptr;   // 1769472
    const float* Wp = nullptr;   // 589824
    for (int i = 0; i < n_in; i++) {
        if (in_sizes[i] == NB * NT * NC)      x  = (const float*)d_in[i];
        else if (in_sizes[i] == 3 * NC * NC)  Wa = (const float*)d_in[i];
        else if (in_sizes[i] == NC * NC)      Wp = (const float*)d_in[i];
    }
    float* out = (float*)d_out;

    cudaFuncSetAttribute(attn_mma,
                         cudaFuncAttributeMaxDynamicSharedMemorySize, ATTN_SMEM);
    cudaFuncSetAttribute(gemm_tf<0>,
                         cudaFuncAttributeMaxDynamicSharedMemorySize, GEMM_SMEM);
    cudaFuncSetAttribute(gemm_tf<1>,
                         cudaFuncAttributeMaxDynamicSharedMemorySize, GEMM_SMEM);

    // 0) one-time rna-tf32 rounding of inputs (zero-mean operand error)
    float* gx;  cudaGetSymbolAddress((void**)&gx,  g_x32);
    float* gwa; cudaGetSymbolAddress((void**)&gwa, g_wa32);
    float* gwp; cudaGetSymbolAddress((void**)&gwp, g_wp32);
    round_tf32<<<(NB * NT * NC) / 1024, 256>>>(x, gx);
    round_tf32<<<(3 * NC * NC) / 1024, 256>>>(Wa, gwa);
    round_tf32<<<(NC * NC) / 1024, 256>>>(Wp, gwp);

    // 1) QKV projection (single-pass tf32), scatter rounded q/k/v
    gemm_tf<0><<<dim3(3 * NC / 64, NB * NT / 128), 256, GEMM_SMEM>>>(nullptr, NC, 3 * NC);

    // 2) causal flash attention -> g_y (rounded fp32)
    attn_mma<<<dim3(NT / 128, NB * NH), 256, ATTN_SMEM>>>();

    // 3) output projection (single-pass tf32)
    gemm_tf<1><<<dim3(NC / 64, NB * NT / 128), 256, GEMM_SMEM>>>(out, NC, NC);
}

// round 15
// speedup vs baseline: 1.7589x; 1.0502x over previous
#include <cuda_runtime.h>
#include <cuda_bf16.h>
#include <math.h>
#include <stdint.h>

#define NB 2
#define NT 2048
#define NC 768
#define NH 12
#define ND 64

// ---------------------------------------------------------------------------
// Device-global scratch. All tensor operands pre-rounded rna-tf32 so tf32 mma
// truncation is exact & unbiased. g_q additionally carries the 1/sqrt(D)=0.125
// scale (power of 2 -> exact).
// ---------------------------------------------------------------------------
__device__ float g_q[NB*NH*NT*ND];     // [b][h][t][d]
__device__ float g_k[NB*NH*NT*ND];
__device__ float g_v[NB*NH*NT*ND];
__device__ float g_y[NB*NT*NC];
__device__ __align__(16) float g_x32[NB*NT*NC];
__device__ __align__(16) float g_wa32[3*NC*NC];
__device__ __align__(16) float g_wp32[NC*NC];

// ---------------------------------------------------------------------------
// helpers
// ---------------------------------------------------------------------------
__device__ __forceinline__ uint32_t smem_to_u32(const void* p) {
    uint32_t a;
    asm("{ .reg .u64 t; cvta.to.shared.u64 t, %1; cvt.u32.u64 %0, t; }"
        : "=r"(a) : "l"(p));
    return a;
}

__device__ __forceinline__ void cp_async16(uint32_t saddr, const void* gptr) {
    asm volatile("cp.async.cg.shared.global [%0], [%1], 16;"
                 :: "r"(saddr), "l"(gptr) : "memory");
}
__device__ __forceinline__ void cp_commit() {
    asm volatile("cp.async.commit_group;" ::: "memory");
}
__device__ __forceinline__ void cp_wait0() {
    asm volatile("cp.async.wait_group 0;" ::: "memory");
}
__device__ __forceinline__ void cp_wait1() {
    asm volatile("cp.async.wait_group 1;" ::: "memory");
}

__device__ __forceinline__ unsigned f2tf32(float x) {
    unsigned r;
    asm("cvt.rna.tf32.f32 %0, %1;" : "=r"(r) : "f"(x));
    return r;
}
__device__ __forceinline__ float rnd_tf32(float x) {
    return __uint_as_float(f2tf32(x));
}

// D += A*B, m16n8k8 tf32
__device__ __forceinline__ void mma_tf32(float c[4], const unsigned a[4],
                                         unsigned b0, unsigned b1) {
    asm volatile(
        "mma.sync.aligned.m16n8k8.row.col.f32.tf32.tf32.f32 "
        "{%0,%1,%2,%3},{%4,%5,%6,%7},{%8,%9},{%0,%1,%2,%3};\n"
        : "+f"(c[0]), "+f"(c[1]), "+f"(c[2]), "+f"(c[3])
        : "r"(a[0]), "r"(a[1]), "r"(a[2]), "r"(a[3]), "r"(b0), "r"(b1));
}

// ---------------------------------------------------------------------------
// One fused rounding kernel: x (3072 blk) | Wa (1728 blk) | Wp (576 blk)
// ---------------------------------------------------------------------------
#define RB_X  (NB*NT*NC/1024)          // 3072
#define RB_WA (3*NC*NC/1024)           // 1728
#define RB_WP (NC*NC/1024)             // 576

__global__ void round_all(const float* __restrict__ x,
                          const float* __restrict__ wa,
                          const float* __restrict__ wp)
{
    int blk = blockIdx.x;
    const float* s;
    float* d;
    if (blk < RB_X)            { s = x;  d = g_x32;  }
    else if (blk < RB_X+RB_WA) { s = wa; d = g_wa32; blk -= RB_X; }
    else                       { s = wp; d = g_wp32; blk -= RB_X + RB_WA; }
    int i4 = (blk * 256 + threadIdx.x) * 4;
    float4 v = *(const float4*)(s + i4);
    v.x = rnd_tf32(v.x); v.y = rnd_tf32(v.y);
    v.z = rnd_tf32(v.z); v.w = rnd_tf32(v.w);
    *(float4*)(d + i4) = v;
}

// ---------------------------------------------------------------------------
// Single-pass TF32 NT GEMM, 3-stage cp.async pipeline, 1 barrier per chunk.
// BM=128, BN=64, BK=32, 256 threads = 8 warps (4m x 2n), warp tile 32x32.
// smem fp32, row stride 36. Loop unrolled x3 -> compile-time stage offsets.
// MODE 0: scatter (rounded; q pre-scaled 0.125) -> g_q/g_k/g_v
// MODE 1: row-major -> Cout
// ---------------------------------------------------------------------------
#define TA_STG (128 * 36)
#define TB_STG (64 * 36)
#define TSTAGE (TA_STG + TB_STG)
#define GEMM_SMEM (3 * TSTAGE * 4)     // 82944 bytes -> 2 CTAs/SM

__device__ __forceinline__ void scat_qkv(int m, int n, float v0, float v1) {
    int b = m >> 11;
    int t = m & 2047;
    int which = n / NC;
    int r = n - which * NC;
    int h = r >> 6;
    int d = r & 63;
    float* dst = (which == 0) ? g_q : (which == 1) ? g_k : g_v;
    float s = (which == 0) ? 0.125f : 1.0f;   // fold 1/sqrt(D) into q (exact)
    *(float2*)(dst + (((size_t)b * NH + h) * NT + t) * ND + d) =
        make_float2(rnd_tf32(v0 * s), rnd_tf32(v1 * s));
}

template<int MODE>
__global__ void __launch_bounds__(256, 2)
gemm_tf(float* __restrict__ Cout, int K, int N)
{
    extern __shared__ __align__(16) float fs[];

    const float* Ag = (MODE == 0) ? g_x32  : g_y;
    const float* Bg = (MODE == 0) ? g_wa32 : g_wp32;

    const uint32_t sb = smem_to_u32(fs);
    const int m0 = blockIdx.y * 128;
    const int n0 = blockIdx.x * 64;
    const int tid = threadIdx.x;
    const int wid = tid >> 5, lane = tid & 31;
    const int g = lane >> 2, t = lane & 3;
    const int wm = wid >> 1, wn = wid & 1;

    const int lrow = tid >> 3, lc4 = (tid & 7) * 4;

    auto load_stage = [&](int s, int k0) {
        #pragma unroll
        for (int i = 0; i < 4; i++) {
            int row = lrow + i * 32;
            cp_async16(sb + (uint32_t)(s * TSTAGE + row * 36 + lc4) * 4,
                       Ag + (size_t)(m0 + row) * K + k0 + lc4);
        }
        #pragma unroll
        for (int i = 0; i < 2; i++) {
            int row = lrow + i * 32;
            cp_async16(sb + (uint32_t)(s * TSTAGE + TA_STG + row * 36 + lc4) * 4,
                       Bg + (size_t)(n0 + row) * K + k0 + lc4);
        }
        cp_commit();
    };

    float acc[2][4][4];
    #pragma unroll
    for (int mt = 0; mt < 2; mt++)
        #pragma unroll
        for (int nt = 0; nt < 4; nt++)
            #pragma unroll
            for (int i = 0; i < 4; i++) acc[mt][nt][i] = 0.0f;

    const int NK = K / 32;               // 24 (divisible by 3)
    load_stage(0, 0);
    load_stage(1, 32);

    for (int c = 0; c < NK; c += 3) {
        #pragma unroll
        for (int u = 0; u < 3; u++) {
            const int cc = c + u;
            cp_wait1();
            __syncthreads();
            // refill buffer (u+2)%3 (its last readers finished pre-barrier)
            if (cc + 2 < NK) load_stage((u + 2) % 3, (cc + 2) * 32);
            else             cp_commit();          // keep group count moving

            const unsigned* As = (const unsigned*)fs + u * TSTAGE;
            const unsigned* Bs = As + TA_STG;

            #pragma unroll
            for (int ks = 0; ks < 4; ks++) {
                const int ko = ks * 8;
                unsigned a[2][4], b[4][2];
                #pragma unroll
                for (int mt = 0; mt < 2; mt++) {
                    int base = (wm * 32 + mt * 16 + g) * 36 + ko + t;
                    a[mt][0] = As[base];
                    a[mt][1] = As[base + 8 * 36];
                    a[mt][2] = As[base + 4];
                    a[mt][3] = As[base + 8 * 36 + 4];
                }
                #pragma unroll
                for (int nt = 0; nt < 4; nt++) {
                    int bb = (wn * 32 + nt * 8 + g) * 36 + ko + t;
                    b[nt][0] = Bs[bb];
                    b[nt][1] = Bs[bb + 4];
                }
                #pragma unroll
                for (int mt = 0; mt < 2; mt++)
                    #pragma unroll
                    for (int nt = 0; nt < 4; nt++)
                        mma_tf32(acc[mt][nt], a[mt], b[nt][0], b[nt][1]);
            }
        }
    }

    #pragma unroll
    for (int mt = 0; mt < 2; mt++) {
        int r0 = m0 + wm * 32 + mt * 16 + g;
        int r1 = r0 + 8;
        #pragma unroll
        for (int nt = 0; nt < 4; nt++) {
            int c = n0 + wn * 32 + nt * 8 + 2 * t;
            if (MODE == 0) {
                scat_qkv(r0, c, acc[mt][nt][0], acc[mt][nt][1]);
                scat_qkv(r1, c, acc[mt][nt][2], acc[mt][nt][3]);
            } else {
                *(float2*)(Cout + (size_t)r0 * N + c) =
                    make_float2(acc[mt][nt][0], acc[mt][nt][1]);
                *(float2*)(Cout + (size_t)r1 * N + c) =
                    make_float2(acc[mt][nt][2], acc[mt][nt][3]);
            }
        }
    }
}

// ---------------------------------------------------------------------------
// Flash attention, tf32 mma.sync (R13 structure; q pre-scaled, no S scaling).
// Q in smem (persistent). K/V cp.async double-buffered. P relayout via
// intra-quad shuffle. One __syncthreads per K-tile. Epilogue -> g_y rounded.
// smem u32: [Q 128x68][stage0: K 64x68 | V 64x72][stage1: same]
// ---------------------------------------------------------------------------
#define AQ_U   (128 * 68)
#define AKV_K  0
#define AKV_V  (64 * 68)
#define AKV_STG (64 * 68 + 64 * 72)
#define ATTN_U (AQ_U + 2 * AKV_STG)
#define ATTN_SMEM (ATTN_U * 4)          // 106496 bytes -> 2 CTAs/SM

__global__ void __launch_bounds__(256, 2) attn_mma()
{
    extern __shared__ __align__(16) unsigned su[];
    const uint32_t sb = smem_to_u32(su);
    unsigned* Qs = su;

    const int qt = (int)gridDim.x - 1 - (int)blockIdx.x;
    const int bh = blockIdx.y;
    const int b = bh / NH;
    const int h = bh - b * NH;
    const int tid = threadIdx.x;
    const int wid = tid >> 5, lane = tid & 31;
    const int g = lane >> 2, t = lane & 3;
    const int R = wid * 16;
    const int odd = t & 1;
    const int srcA = (lane & ~3) | (t >> 1);
    const int srcB = srcA + 2;

    const size_t head_base = ((size_t)b * NH + h) * (size_t)NT * ND;
    const int q0 = qt * 128;

    {
        const float* qg = g_q + head_base + (size_t)q0 * ND;
        #pragma unroll
        for (int i = 0; i < 8; i++) {
            int idx = tid + i * 256;
            int row = idx >> 4, d4 = (idx & 15) << 2;
            *(uint4*)(Qs + row * 68 + d4) = *(const uint4*)(qg + row * ND + d4);
        }
    }

    const int kt_max = 2 * qt + 1;

    auto issue_kv = [&](int s, int k0) {
        const float* kg = g_k + head_base + (size_t)k0 * ND;
        const float* vg = g_v + head_base + (size_t)k0 * ND;
        #pragma unroll
        for (int i = 0; i < 4; i++) {
            int idx = tid + i * 256;
            int row = idx >> 4, c4 = (idx & 15) << 2;
            cp_async16(sb + (uint32_t)(AQ_U + s * AKV_STG + AKV_K + row * 68 + c4) * 4,
                       kg + row * ND + c4);
            cp_async16(sb + (uint32_t)(AQ_U + s * AKV_STG + AKV_V + row * 72 + c4) * 4,
                       vg + row * ND + c4);
        }
        cp_commit();
    };

    issue_kv(0, 0);

    float mrow[2] = {-1e30f, -1e30f};
    float lrow[2] = {0.0f, 0.0f};
    float o[8][4];
    #pragma unroll
    for (int nt = 0; nt < 8; nt++)
        #pragma unroll
        for (int i = 0; i < 4; i++) o[nt][i] = 0.0f;

    for (int kt = 0; kt <= kt_max; kt++) {
        cp_wait0();
        __syncthreads();
        if (kt + 1 <= kt_max) issue_kv((kt + 1) & 1, (kt + 1) * 64);

        const unsigned* Ks = su + AQ_U + (kt & 1) * AKV_STG + AKV_K;
        const unsigned* Vs = su + AQ_U + (kt & 1) * AKV_STG + AKV_V;
        const int k0 = kt * 64;

        // ---- S = Q K^T  (q pre-scaled by 0.125) ----
        float sc[8][4];
        #pragma unroll
        for (int nt = 0; nt < 8; nt++)
            #pragma unroll
            for (int i = 0; i < 4; i++) sc[nt][i] = 0.0f;

        #pragma unroll
        for (int ks = 0; ks < 8; ks++) {
            unsigned a[4];
            int ra = (R + g) * 68 + ks * 8 + t;
            int rb = (R + g + 8) * 68 + ks * 8 + t;
            a[0] = Qs[ra]; a[1] = Qs[rb]; a[2] = Qs[ra + 4]; a[3] = Qs[rb + 4];
            #pragma unroll
            for (int nt = 0; nt < 8; nt++) {
                int kb = (nt * 8 + g) * 68 + ks * 8 + t;
                mma_tf32(sc[nt], a, Ks[kb], Ks[kb + 4]);
            }
        }

        // ---- causal mask (no scaling needed) ----
        const bool nm = (kt >= 2 * qt);
        if (nm) {
            const int rlo = q0 + R + g;
            const int rhi = rlo + 8;
            #pragma unroll
            for (int nt = 0; nt < 8; nt++) {
                int cc = k0 + nt * 8 + 2 * t;
                if (cc > rlo)     sc[nt][0] = -1e30f;
                if (cc + 1 > rlo) sc[nt][1] = -1e30f;
                if (cc > rhi)     sc[nt][2] = -1e30f;
                if (cc + 1 > rhi) sc[nt][3] = -1e30f;
            }
        }

        // ---- online softmax ----
        float mx0 = -1e30f, mx1 = -1e30f;
        #pragma unroll
        for (int nt = 0; nt < 8; nt++) {
            mx0 = fmaxf(mx0, fmaxf(sc[nt][0], sc[nt][1]));
            mx1 = fmaxf(mx1, fmaxf(sc[nt][2], sc[nt][3]));
        }
        mx0 = fmaxf(mx0, __shfl_xor_sync(0xffffffffu, mx0, 1));
        mx0 = fmaxf(mx0, __shfl_xor_sync(0xffffffffu, mx0, 2));
        mx1 = fmaxf(mx1, __shfl_xor_sync(0xffffffffu, mx1, 1));
        mx1 = fmaxf(mx1, __shfl_xor_sync(0xffffffffu, mx1, 2));

        float mn0 = fmaxf(mrow[0], mx0);
        float mn1 = fmaxf(mrow[1], mx1);
        float al0 = __expf(mrow[0] - mn0);
        float al1 = __expf(mrow[1] - mn1);
        mrow[0] = mn0; mrow[1] = mn1;

        float rs0 = 0.0f, rs1 = 0.0f;
        #pragma unroll
        for (int nt = 0; nt < 8; nt++) {
            sc[nt][0] = __expf(sc[nt][0] - mn0); rs0 += sc[nt][0];
            sc[nt][1] = __expf(sc[nt][1] - mn0); rs0 += sc[nt][1];
            sc[nt][2] = __expf(sc[nt][2] - mn1); rs1 += sc[nt][2];
            sc[nt][3] = __expf(sc[nt][3] - mn1); rs1 += sc[nt][3];
        }
        rs0 += __shfl_xor_sync(0xffffffffu, rs0, 1);
        rs0 += __shfl_xor_sync(0xffffffffu, rs0, 2);
        rs1 += __shfl_xor_sync(0xffffffffu, rs1, 1);
        rs1 += __shfl_xor_sync(0xffffffffu, rs1, 2);
        lrow[0] = lrow[0] * al0 + rs0;
        lrow[1] = lrow[1] * al1 + rs1;

        #pragma unroll
        for (int nt = 0; nt < 8; nt++) {
            o[nt][0] *= al0; o[nt][1] *= al0;
            o[nt][2] *= al1; o[nt][3] *= al1;
        }

        // ---- O += P V : P A-fragments via intra-quad shuffle ----
        #pragma unroll
        for (int ks = 0; ks < 8; ks++) {
            unsigned p0 = f2tf32(sc[ks][0]);
            unsigned p1 = f2tf32(sc[ks][1]);
            unsigned p2 = f2tf32(sc[ks][2]);
            unsigned p3 = f2tf32(sc[ks][3]);
            unsigned u0 = __shfl_sync(0xffffffffu, p0, srcA);
            unsigned u1 = __shfl_sync(0xffffffffu, p1, srcA);
            unsigned u2 = __shfl_sync(0xffffffffu, p2, srcA);
            unsigned u3 = __shfl_sync(0xffffffffu, p3, srcA);
            unsigned w0 = __shfl_sync(0xffffffffu, p0, srcB);
            unsigned w1 = __shfl_sync(0xffffffffu, p1, srcB);
            unsigned w2 = __shfl_sync(0xffffffffu, p2, srcB);
            unsigned w3 = __shfl_sync(0xffffffffu, p3, srcB);
            unsigned a[4];
            a[0] = odd ? u1 : u0;
            a[1] = odd ? u3 : u2;
            a[2] = odd ? w1 : w0;
            a[3] = odd ? w3 : w2;
            #pragma unroll
            for (int nt = 0; nt < 8; nt++) {
                int v0 = (ks * 8 + t) * 72 + nt * 8 + g;
                int v1 = (ks * 8 + t + 4) * 72 + nt * 8 + g;
                mma_tf32(o[nt], a, Vs[v0], Vs[v1]);
            }
        }
    }

    // ---- epilogue: normalize; write rounded fp32 y ----
    float i0 = 1.0f / lrow[0];
    float i1 = 1.0f / lrow[1];
    size_t base0 = ((size_t)b * NT + (q0 + R + g)) * NC + h * ND;
    size_t base1 = ((size_t)b * NT + (q0 + R + g + 8)) * NC + h * ND;
    #pragma unroll
    for (int nt = 0; nt < 8; nt++) {
        size_t off0 = base0 + nt * 8 + 2 * t;
        size_t off1 = base1 + nt * 8 + 2 * t;
        *(float2*)(g_y + off0) = make_float2(rnd_tf32(o[nt][0] * i0),
                                             rnd_tf32(o[nt][1] * i0));
        *(float2*)(g_y + off1) = make_float2(rnd_tf32(o[nt][2] * i1),
                                             rnd_tf32(o[nt][3] * i1));
    }
}

// ---------------------------------------------------------------------------
extern "C" void kernel_launch(void* const* d_in, const int* in_sizes, int n_in,
                              void* d_out, int out_size)
{
    const float* x  = nullptr;   // 3145728
    const float* Wa = nullptr;   // 1769472
    const float* Wp = nullptr;   // 589824
    for (int i = 0; i < n_in; i++) {
        if (in_sizes[i] == NB * NT * NC)      x  = (const float*)d_in[i];
        else if (in_sizes[i] == 3 * NC * NC)  Wa = (const float*)d_in[i];
        else if (in_sizes[i] == NC * NC)      Wp = (const float*)d_in[i];
    }
    float* out = (float*)d_out;

    cudaFuncSetAttribute(attn_mma,
                         cudaFuncAttributeMaxDynamicSharedMemorySize, ATTN_SMEM);
    cudaFuncSetAttribute(gemm_tf<0>,
                         cudaFuncAttributeMaxDynamicSharedMemorySize, GEMM_SMEM);
    cudaFuncSetAttribute(gemm_tf<1>,
                         cudaFuncAttributeMaxDynamicSharedMemorySize, GEMM_SMEM);

    // 0) fused one-time rna-tf32 rounding
    round_all<<<RB_X + RB_WA + RB_WP, 256>>>(x, Wa, Wp);

    // 1) QKV projection (tf32, 3-stage pipeline), scatter q(*0.125)/k/v
    gemm_tf<0><<<dim3(3 * NC / 64, NB * NT / 128), 256, GEMM_SMEM>>>(nullptr, NC, 3 * NC);

    // 2) causal flash attention -> g_y
    attn_mma<<<dim3(NT / 128, NB * NH), 256, ATTN_SMEM>>>();

    // 3) output projection
    gemm_tf<1><<<dim3(NC / 64, NB * NT / 128), 256, GEMM_SMEM>>>(out, NC, NC);
}

// round 16
// speedup vs baseline: 1.8888x; 1.0738x over previous
#include <cuda_runtime.h>
#include <cuda_bf16.h>
#include <math.h>
#include <stdint.h>

#define NB 2
#define NT 2048
#define NC 768
#define NH 12
#define ND 64

// ---------------------------------------------------------------------------
// Device-global scratch. All tensor operands pre-rounded rna-tf32 so tf32 mma
// truncation is exact & unbiased. g_q carries the 1/sqrt(D)=0.125 scale.
// ---------------------------------------------------------------------------
__device__ float g_q[NB*NH*NT*ND];     // [b][h][t][d]
__device__ float g_k[NB*NH*NT*ND];
__device__ float g_v[NB*NH*NT*ND];
__device__ float g_y[NB*NT*NC];
__device__ __align__(16) float g_x32[NB*NT*NC];
__device__ __align__(16) float g_wa32[3*NC*NC];
__device__ __align__(16) float g_wp32[NC*NC];

// ---------------------------------------------------------------------------
// helpers
// ---------------------------------------------------------------------------
__device__ __forceinline__ uint32_t smem_to_u32(const void* p) {
    uint32_t a;
    asm("{ .reg .u64 t; cvta.to.shared.u64 t, %1; cvt.u32.u64 %0, t; }"
        : "=r"(a) : "l"(p));
    return a;
}

__device__ __forceinline__ void cp_async16(uint32_t saddr, const void* gptr) {
    asm volatile("cp.async.cg.shared.global [%0], [%1], 16;"
                 :: "r"(saddr), "l"(gptr) : "memory");
}
__device__ __forceinline__ void cp_commit() {
    asm volatile("cp.async.commit_group;" ::: "memory");
}
__device__ __forceinline__ void cp_wait0() {
    asm volatile("cp.async.wait_group 0;" ::: "memory");
}
__device__ __forceinline__ void cp_wait1() {
    asm volatile("cp.async.wait_group 1;" ::: "memory");
}

__device__ __forceinline__ unsigned f2tf32(float x) {
    unsigned r;
    asm("cvt.rna.tf32.f32 %0, %1;" : "=r"(r) : "f"(x));
    return r;
}
__device__ __forceinline__ float rnd_tf32(float x) {
    return __uint_as_float(f2tf32(x));
}

// D += A*B, m16n8k8 tf32
__device__ __forceinline__ void mma_tf32(float c[4], const unsigned a[4],
                                         unsigned b0, unsigned b1) {
    asm volatile(
        "mma.sync.aligned.m16n8k8.row.col.f32.tf32.tf32.f32 "
        "{%0,%1,%2,%3},{%4,%5,%6,%7},{%8,%9},{%0,%1,%2,%3};\n"
        : "+f"(c[0]), "+f"(c[1]), "+f"(c[2]), "+f"(c[3])
        : "r"(a[0]), "r"(a[1]), "r"(a[2]), "r"(a[3]), "r"(b0), "r"(b1));
}

// ---------------------------------------------------------------------------
// One fused rounding kernel: x | Wa | Wp
// ---------------------------------------------------------------------------
#define RB_X  (NB*NT*NC/1024)          // 3072
#define RB_WA (3*NC*NC/1024)           // 1728
#define RB_WP (NC*NC/1024)             // 576

__global__ void round_all(const float* __restrict__ x,
                          const float* __restrict__ wa,
                          const float* __restrict__ wp)
{
    int blk = blockIdx.x;
    const float* s;
    float* d;
    if (blk < RB_X)            { s = x;  d = g_x32;  }
    else if (blk < RB_X+RB_WA) { s = wa; d = g_wa32; blk -= RB_X; }
    else                       { s = wp; d = g_wp32; blk -= RB_X + RB_WA; }
    int i4 = (blk * 256 + threadIdx.x) * 4;
    float4 v = *(const float4*)(s + i4);
    v.x = rnd_tf32(v.x); v.y = rnd_tf32(v.y);
    v.z = rnd_tf32(v.z); v.w = rnd_tf32(v.w);
    *(float4*)(d + i4) = v;
}

__device__ __forceinline__ void scat_qkv(int m, int n, float v0, float v1) {
    int b = m >> 11;
    int t = m & 2047;
    int which = n / NC;
    int r = n - which * NC;
    int h = r >> 6;
    int d = r & 63;
    float* dst = (which == 0) ? g_q : (which == 1) ? g_k : g_v;
    float s = (which == 0) ? 0.125f : 1.0f;   // fold 1/sqrt(D) into q (exact)
    *(float2*)(dst + (((size_t)b * NH + h) * NT + t) * ND + d) =
        make_float2(rnd_tf32(v0 * s), rnd_tf32(v1 * s));
}

// ---------------------------------------------------------------------------
// QKV GEMM: BM=128, BN=128, BK=32. 8 warps as 2m x 4n, warp tile 64x32.
// 25% fewer crossbar bytes than 128x64 config; loads/mma 2.0 -> 1.5.
// 3-stage cp.async pipeline, 1 barrier/chunk. A-frags consumed immediately
// per mt to cap register pressure (acc 64 + b 8 + a 4 live).
// ---------------------------------------------------------------------------
#define QA_STG (128 * 36)
#define QSTAGE (2 * QA_STG)
#define QKV_SMEM (3 * QSTAGE * 4)      // 110592 bytes -> 2 CTAs/SM

__global__ void __launch_bounds__(256, 2)
gemm_qkv()
{
    extern __shared__ __align__(16) float fs[];
    constexpr int K = NC;              // 768

    const uint32_t sb = smem_to_u32(fs);
    const int m0 = blockIdx.y * 128;
    const int n0 = blockIdx.x * 128;
    const int tid = threadIdx.x;
    const int wid = tid >> 5, lane = tid & 31;
    const int g = lane >> 2, t = lane & 3;
    const int wm = wid >> 2, wn = wid & 3;   // 2m x 4n

    const int lrow = tid >> 3, lc4 = (tid & 7) * 4;

    auto load_stage = [&](int s, int k0) {
        #pragma unroll
        for (int i = 0; i < 4; i++) {
            int row = lrow + i * 32;
            cp_async16(sb + (uint32_t)(s * QSTAGE + row * 36 + lc4) * 4,
                       g_x32 + (size_t)(m0 + row) * K + k0 + lc4);
        }
        #pragma unroll
        for (int i = 0; i < 4; i++) {
            int row = lrow + i * 32;
            cp_async16(sb + (uint32_t)(s * QSTAGE + QA_STG + row * 36 + lc4) * 4,
                       g_wa32 + (size_t)(n0 + row) * K + k0 + lc4);
        }
        cp_commit();
    };

    float acc[4][4][4];
    #pragma unroll
    for (int mt = 0; mt < 4; mt++)
        #pragma unroll
        for (int nt = 0; nt < 4; nt++)
            #pragma unroll
            for (int i = 0; i < 4; i++) acc[mt][nt][i] = 0.0f;

    const int NK = K / 32;             // 24
    load_stage(0, 0);
    load_stage(1, 32);

    for (int c = 0; c < NK; c += 3) {
        #pragma unroll
        for (int u = 0; u < 3; u++) {
            const int cc = c + u;
            cp_wait1();
            __syncthreads();
            if (cc + 2 < NK) load_stage((u + 2) % 3, (cc + 2) * 32);
            else             cp_commit();

            const unsigned* As = (const unsigned*)fs + u * QSTAGE;
            const unsigned* Bs = As + QA_STG;

            #pragma unroll
            for (int ks = 0; ks < 4; ks++) {
                const int ko = ks * 8;
                unsigned b[4][2];
                #pragma unroll
                for (int nt = 0; nt < 4; nt++) {
                    int bb = (wn * 32 + nt * 8 + g) * 36 + ko + t;
                    b[nt][0] = Bs[bb];
                    b[nt][1] = Bs[bb + 4];
                }
                #pragma unroll
                for (int mt = 0; mt < 4; mt++) {
                    unsigned a[4];
                    int base = (wm * 64 + mt * 16 + g) * 36 + ko + t;
                    a[0] = As[base];
                    a[1] = As[base + 8 * 36];
                    a[2] = As[base + 4];
                    a[3] = As[base + 8 * 36 + 4];
                    #pragma unroll
                    for (int nt = 0; nt < 4; nt++)
                        mma_tf32(acc[mt][nt], a, b[nt][0], b[nt][1]);
                }
            }
        }
    }

    #pragma unroll
    for (int mt = 0; mt < 4; mt++) {
        int r0 = m0 + wm * 64 + mt * 16 + g;
        int r1 = r0 + 8;
        #pragma unroll
        for (int nt = 0; nt < 4; nt++) {
            int c = n0 + wn * 32 + nt * 8 + 2 * t;
            scat_qkv(r0, c, acc[mt][nt][0], acc[mt][nt][1]);
            scat_qkv(r1, c, acc[mt][nt][2], acc[mt][nt][3]);
        }
    }
}

// ---------------------------------------------------------------------------
// Proj GEMM (unchanged from R15): BM=128, BN=64, 3-stage pipeline.
// ---------------------------------------------------------------------------
#define TA_STG (128 * 36)
#define TB_STG (64 * 36)
#define TSTAGE (TA_STG + TB_STG)
#define GEMM_SMEM (3 * TSTAGE * 4)     // 82944 bytes

__global__ void __launch_bounds__(256, 2)
gemm_proj(float* __restrict__ Cout)
{
    extern __shared__ __align__(16) float fs[];
    constexpr int K = NC, N = NC;

    const uint32_t sb = smem_to_u32(fs);
    const int m0 = blockIdx.y * 128;
    const int n0 = blockIdx.x * 64;
    const int tid = threadIdx.x;
    const int wid = tid >> 5, lane = tid & 31;
    const int g = lane >> 2, t = lane & 3;
    const int wm = wid >> 1, wn = wid & 1;

    const int lrow = tid >> 3, lc4 = (tid & 7) * 4;

    auto load_stage = [&](int s, int k0) {
        #pragma unroll
        for (int i = 0; i < 4; i++) {
            int row = lrow + i * 32;
            cp_async16(sb + (uint32_t)(s * TSTAGE + row * 36 + lc4) * 4,
                       g_y + (size_t)(m0 + row) * K + k0 + lc4);
        }
        #pragma unroll
        for (int i = 0; i < 2; i++) {
            int row = lrow + i * 32;
            cp_async16(sb + (uint32_t)(s * TSTAGE + TA_STG + row * 36 + lc4) * 4,
                       g_wp32 + (size_t)(n0 + row) * K + k0 + lc4);
        }
        cp_commit();
    };

    float acc[2][4][4];
    #pragma unroll
    for (int mt = 0; mt < 2; mt++)
        #pragma unroll
        for (int nt = 0; nt < 4; nt++)
            #pragma unroll
            for (int i = 0; i < 4; i++) acc[mt][nt][i] = 0.0f;

    const int NK = K / 32;
    load_stage(0, 0);
    load_stage(1, 32);

    for (int c = 0; c < NK; c += 3) {
        #pragma unroll
        for (int u = 0; u < 3; u++) {
            const int cc = c + u;
            cp_wait1();
            __syncthreads();
            if (cc + 2 < NK) load_stage((u + 2) % 3, (cc + 2) * 32);
            else             cp_commit();

            const unsigned* As = (const unsigned*)fs + u * TSTAGE;
            const unsigned* Bs = As + TA_STG;

            #pragma unroll
            for (int ks = 0; ks < 4; ks++) {
                const int ko = ks * 8;
                unsigned a[2][4], b[4][2];
                #pragma unroll
                for (int mt = 0; mt < 2; mt++) {
                    int base = (wm * 32 + mt * 16 + g) * 36 + ko + t;
                    a[mt][0] = As[base];
                    a[mt][1] = As[base + 8 * 36];
                    a[mt][2] = As[base + 4];
                    a[mt][3] = As[base + 8 * 36 + 4];
                }
                #pragma unroll
                for (int nt = 0; nt < 4; nt++) {
                    int bb = (wn * 32 + nt * 8 + g) * 36 + ko + t;
                    b[nt][0] = Bs[bb];
                    b[nt][1] = Bs[bb + 4];
                }
                #pragma unroll
                for (int mt = 0; mt < 2; mt++)
                    #pragma unroll
                    for (int nt = 0; nt < 4; nt++)
                        mma_tf32(acc[mt][nt], a[mt], b[nt][0], b[nt][1]);
            }
        }
    }

    #pragma unroll
    for (int mt = 0; mt < 2; mt++) {
        int r0 = m0 + wm * 32 + mt * 16 + g;
        int r1 = r0 + 8;
        #pragma unroll
        for (int nt = 0; nt < 4; nt++) {
            int c = n0 + wn * 32 + nt * 8 + 2 * t;
            *(float2*)(Cout + (size_t)r0 * N + c) =
                make_float2(acc[mt][nt][0], acc[mt][nt][1]);
            *(float2*)(Cout + (size_t)r1 * N + c) =
                make_float2(acc[mt][nt][2], acc[mt][nt][3]);
        }
    }
}

// ---------------------------------------------------------------------------
// Flash attention, tf32 mma.sync (unchanged from R15).
// ---------------------------------------------------------------------------
#define AQ_U   (128 * 68)
#define AKV_K  0
#define AKV_V  (64 * 68)
#define AKV_STG (64 * 68 + 64 * 72)
#define ATTN_U (AQ_U + 2 * AKV_STG)
#define ATTN_SMEM (ATTN_U * 4)          // 106496 bytes -> 2 CTAs/SM

__global__ void __launch_bounds__(256, 2) attn_mma()
{
    extern __shared__ __align__(16) unsigned su[];
    const uint32_t sb = smem_to_u32(su);
    unsigned* Qs = su;

    const int qt = (int)gridDim.x - 1 - (int)blockIdx.x;
    const int bh = blockIdx.y;
    const int b = bh / NH;
    const int h = bh - b * NH;
    const int tid = threadIdx.x;
    const int wid = tid >> 5, lane = tid & 31;
    const int g = lane >> 2, t = lane & 3;
    const int R = wid * 16;
    const int odd = t & 1;
    const int srcA = (lane & ~3) | (t >> 1);
    const int srcB = srcA + 2;

    const size_t head_base = ((size_t)b * NH + h) * (size_t)NT * ND;
    const int q0 = qt * 128;

    {
        const float* qg = g_q + head_base + (size_t)q0 * ND;
        #pragma unroll
        for (int i = 0; i < 8; i++) {
            int idx = tid + i * 256;
            int row = idx >> 4, d4 = (idx & 15) << 2;
            *(uint4*)(Qs + row * 68 + d4) = *(const uint4*)(qg + row * ND + d4);
        }
    }

    const int kt_max = 2 * qt + 1;

    auto issue_kv = [&](int s, int k0) {
        const float* kg = g_k + head_base + (size_t)k0 * ND;
        const float* vg = g_v + head_base + (size_t)k0 * ND;
        #pragma unroll
        for (int i = 0; i < 4; i++) {
            int idx = tid + i * 256;
            int row = idx >> 4, c4 = (idx & 15) << 2;
            cp_async16(sb + (uint32_t)(AQ_U + s * AKV_STG + AKV_K + row * 68 + c4) * 4,
                       kg + row * ND + c4);
            cp_async16(sb + (uint32_t)(AQ_U + s * AKV_STG + AKV_V + row * 72 + c4) * 4,
                       vg + row * ND + c4);
        }
        cp_commit();
    };

    issue_kv(0, 0);

    float mrow[2] = {-1e30f, -1e30f};
    float lrow[2] = {0.0f, 0.0f};
    float o[8][4];
    #pragma unroll
    for (int nt = 0; nt < 8; nt++)
        #pragma unroll
        for (int i = 0; i < 4; i++) o[nt][i] = 0.0f;

    for (int kt = 0; kt <= kt_max; kt++) {
        cp_wait0();
        __syncthreads();
        if (kt + 1 <= kt_max) issue_kv((kt + 1) & 1, (kt + 1) * 64);

        const unsigned* Ks = su + AQ_U + (kt & 1) * AKV_STG + AKV_K;
        const unsigned* Vs = su + AQ_U + (kt & 1) * AKV_STG + AKV_V;
        const int k0 = kt * 64;

        float sc[8][4];
        #pragma unroll
        for (int nt = 0; nt < 8; nt++)
            #pragma unroll
            for (int i = 0; i < 4; i++) sc[nt][i] = 0.0f;

        #pragma unroll
        for (int ks = 0; ks < 8; ks++) {
            unsigned a[4];
            int ra = (R + g) * 68 + ks * 8 + t;
            int rb = (R + g + 8) * 68 + ks * 8 + t;
            a[0] = Qs[ra]; a[1] = Qs[rb]; a[2] = Qs[ra + 4]; a[3] = Qs[rb + 4];
            #pragma unroll
            for (int nt = 0; nt < 8; nt++) {
                int kb = (nt * 8 + g) * 68 + ks * 8 + t;
                mma_tf32(sc[nt], a, Ks[kb], Ks[kb + 4]);
            }
        }

        const bool nm = (kt >= 2 * qt);
        if (nm) {
            const int rlo = q0 + R + g;
            const int rhi = rlo + 8;
            #pragma unroll
            for (int nt = 0; nt < 8; nt++) {
                int cc = k0 + nt * 8 + 2 * t;
                if (cc > rlo)     sc[nt][0] = -1e30f;
                if (cc + 1 > rlo) sc[nt][1] = -1e30f;
                if (cc > rhi)     sc[nt][2] = -1e30f;
                if (cc + 1 > rhi) sc[nt][3] = -1e30f;
            }
        }

        float mx0 = -1e30f, mx1 = -1e30f;
        #pragma unroll
        for (int nt = 0; nt < 8; nt++) {
            mx0 = fmaxf(mx0, fmaxf(sc[nt][0], sc[nt][1]));
            mx1 = fmaxf(mx1, fmaxf(sc[nt][2], sc[nt][3]));
        }
        mx0 = fmaxf(mx0, __shfl_xor_sync(0xffffffffu, mx0, 1));
        mx0 = fmaxf(mx0, __shfl_xor_sync(0xffffffffu, mx0, 2));
        mx1 = fmaxf(mx1, __shfl_xor_sync(0xffffffffu, mx1, 1));
        mx1 = fmaxf(mx1, __shfl_xor_sync(0xffffffffu, mx1, 2));

        float mn0 = fmaxf(mrow[0], mx0);
        float mn1 = fmaxf(mrow[1], mx1);
        float al0 = __expf(mrow[0] - mn0);
        float al1 = __expf(mrow[1] - mn1);
        mrow[0] = mn0; mrow[1] = mn1;

        float rs0 = 0.0f, rs1 = 0.0f;
        #pragma unroll
        for (int nt = 0; nt < 8; nt++) {
            sc[nt][0] = __expf(sc[nt][0] - mn0); rs0 += sc[nt][0];
            sc[nt][1] = __expf(sc[nt][1] - mn0); rs0 += sc[nt][1];
            sc[nt][2] = __expf(sc[nt][2] - mn1); rs1 += sc[nt][2];
            sc[nt][3] = __expf(sc[nt][3] - mn1); rs1 += sc[nt][3];
        }
        rs0 += __shfl_xor_sync(0xffffffffu, rs0, 1);
        rs0 += __shfl_xor_sync(0xffffffffu, rs0, 2);
        rs1 += __shfl_xor_sync(0xffffffffu, rs1, 1);
        rs1 += __shfl_xor_sync(0xffffffffu, rs1, 2);
        lrow[0] = lrow[0] * al0 + rs0;
        lrow[1] = lrow[1] * al1 + rs1;

        #pragma unroll
        for (int nt = 0; nt < 8; nt++) {
            o[nt][0] *= al0; o[nt][1] *= al0;
            o[nt][2] *= al1; o[nt][3] *= al1;
        }

        #pragma unroll
        for (int ks = 0; ks < 8; ks++) {
            unsigned p0 = f2tf32(sc[ks][0]);
            unsigned p1 = f2tf32(sc[ks][1]);
            unsigned p2 = f2tf32(sc[ks][2]);
            unsigned p3 = f2tf32(sc[ks][3]);
            unsigned u0 = __shfl_sync(0xffffffffu, p0, srcA);
            unsigned u1 = __shfl_sync(0xffffffffu, p1, srcA);
            unsigned u2 = __shfl_sync(0xffffffffu, p2, srcA);
            unsigned u3 = __shfl_sync(0xffffffffu, p3, srcA);
            unsigned w0 = __shfl_sync(0xffffffffu, p0, srcB);
            unsigned w1 = __shfl_sync(0xffffffffu, p1, srcB);
            unsigned w2 = __shfl_sync(0xffffffffu, p2, srcB);
            unsigned w3 = __shfl_sync(0xffffffffu, p3, srcB);
            unsigned a[4];
            a[0] = odd ? u1 : u0;
            a[1] = odd ? u3 : u2;
            a[2] = odd ? w1 : w0;
            a[3] = odd ? w3 : w2;
            #pragma unroll
            for (int nt = 0; nt < 8; nt++) {
                int v0 = (ks * 8 + t) * 72 + nt * 8 + g;
                int v1 = (ks * 8 + t + 4) * 72 + nt * 8 + g;
                mma_tf32(o[nt], a, Vs[v0], Vs[v1]);
            }
        }
    }

    float i0 = 1.0f / lrow[0];
    float i1 = 1.0f / lrow[1];
    size_t base0 = ((size_t)b * NT + (q0 + R + g)) * NC + h * ND;
    size_t base1 = ((size_t)b * NT + (q0 + R + g + 8)) * NC + h * ND;
    #pragma unroll
    for (int nt = 0; nt < 8; nt++) {
        size_t off0 = base0 + nt * 8 + 2 * t;
        size_t off1 = base1 + nt * 8 + 2 * t;
        *(float2*)(g_y + off0) = make_float2(rnd_tf32(o[nt][0] * i0),
                                             rnd_tf32(o[nt][1] * i0));
        *(float2*)(g_y + off1) = make_float2(rnd_tf32(o[nt][2] * i1),
                                             rnd_tf32(o[nt][3] * i1));
    }
}

// ---------------------------------------------------------------------------
extern "C" void kernel_launch(void* const* d_in, const int* in_sizes, int n_in,
                              void* d_out, int out_size)
{
    const float* x  = nullptr;   // 3145728
    const float* Wa = nullptr;   // 1769472
    const float* Wp = nullptr;   // 589824
    for (int i = 0; i < n_in; i++) {
        if (in_sizes[i] == NB * NT * NC)      x  = (const float*)d_in[i];
        else if (in_sizes[i] == 3 * NC * NC)  Wa = (const float*)d_in[i];
        else if (in_sizes[i] == NC * NC)      Wp = (const float*)d_in[i];
    }
    float* out = (float*)d_out;

    cudaFuncSetAttribute(attn_mma,
                         cudaFuncAttributeMaxDynamicSharedMemorySize, ATTN_SMEM);
    cudaFuncSetAttribute(gemm_qkv,
                         cudaFuncAttributeMaxDynamicSharedMemorySize, QKV_SMEM);
    cudaFuncSetAttribute(gemm_proj,
                         cudaFuncAttributeMaxDynamicSharedMemorySize, GEMM_SMEM);

    // 0) fused one-time rna-tf32 rounding
    round_all<<<RB_X + RB_WA + RB_WP, 256>>>(x, Wa, Wp);

    // 1) QKV projection (128x128 tiles, 64x32 warp tiles), scatter q/k/v
    gemm_qkv<<<dim3(3 * NC / 128, NB * NT / 128), 256, QKV_SMEM>>>();

    // 2) causal flash attention -> g_y
    attn_mma<<<dim3(NT / 128, NB * NH), 256, ATTN_SMEM>>>();

    // 3) output projection
    gemm_proj<<<dim3(NC / 64, NB * NT / 128), 256, GEMM_SMEM>>>(out);
}

// round 17
// speedup vs baseline: 1.8912x; 1.0013x over previous
#include <cuda_runtime.h>
#include <cuda_bf16.h>
#include <math.h>
#include <stdint.h>

#define NB 2
#define NT 2048
#define NC 768
#define NH 12
#define ND 64

// ---------------------------------------------------------------------------
// Device-global scratch. All tensor operands pre-rounded rna-tf32 so tf32 mma
// truncation is exact & unbiased. g_q carries 0.125*log2(e) (softmax in base 2).
// ---------------------------------------------------------------------------
__device__ float g_q[NB*NH*NT*ND];     // [b][h][t][d]
__device__ float g_k[NB*NH*NT*ND];
__device__ float g_v[NB*NH*NT*ND];
__device__ float g_y[NB*NT*NC];
__device__ __align__(16) float g_x32[NB*NT*NC];
__device__ __align__(16) float g_wa32[3*NC*NC];
__device__ __align__(16) float g_wp32[NC*NC];

// ---------------------------------------------------------------------------
// helpers
// ---------------------------------------------------------------------------
__device__ __forceinline__ uint32_t smem_to_u32(const void* p) {
    uint32_t a;
    asm("{ .reg .u64 t; cvta.to.shared.u64 t, %1; cvt.u32.u64 %0, t; }"
        : "=r"(a) : "l"(p));
    return a;
}

__device__ __forceinline__ void cp_async16(uint32_t saddr, const void* gptr) {
    asm volatile("cp.async.cg.shared.global [%0], [%1], 16;"
                 :: "r"(saddr), "l"(gptr) : "memory");
}
__device__ __forceinline__ void cp_commit() {
    asm volatile("cp.async.commit_group;" ::: "memory");
}
__device__ __forceinline__ void cp_wait0() {
    asm volatile("cp.async.wait_group 0;" ::: "memory");
}
__device__ __forceinline__ void cp_wait1() {
    asm volatile("cp.async.wait_group 1;" ::: "memory");
}

__device__ __forceinline__ unsigned f2tf32(float x) {
    unsigned r;
    asm("cvt.rna.tf32.f32 %0, %1;" : "=r"(r) : "f"(x));
    return r;
}
__device__ __forceinline__ float rnd_tf32(float x) {
    return __uint_as_float(f2tf32(x));
}
__device__ __forceinline__ float ex2(float x) {     // 2^x, MUFU only
    float r;
    asm("ex2.approx.ftz.f32 %0, %1;" : "=f"(r) : "f"(x));
    return r;
}

// D += A*B, m16n8k8 tf32
__device__ __forceinline__ void mma_tf32(float c[4], const unsigned a[4],
                                         unsigned b0, unsigned b1) {
    asm volatile(
        "mma.sync.aligned.m16n8k8.row.col.f32.tf32.tf32.f32 "
        "{%0,%1,%2,%3},{%4,%5,%6,%7},{%8,%9},{%0,%1,%2,%3};\n"
        : "+f"(c[0]), "+f"(c[1]), "+f"(c[2]), "+f"(c[3])
        : "r"(a[0]), "r"(a[1]), "r"(a[2]), "r"(a[3]), "r"(b0), "r"(b1));
}

// ---------------------------------------------------------------------------
// One fused rounding kernel: x | Wa | Wp
// ---------------------------------------------------------------------------
#define RB_X  (NB*NT*NC/1024)          // 3072
#define RB_WA (3*NC*NC/1024)           // 1728
#define RB_WP (NC*NC/1024)             // 576

__global__ void round_all(const float* __restrict__ x,
                          const float* __restrict__ wa,
                          const float* __restrict__ wp)
{
    int blk = blockIdx.x;
    const float* s;
    float* d;
    if (blk < RB_X)            { s = x;  d = g_x32;  }
    else if (blk < RB_X+RB_WA) { s = wa; d = g_wa32; blk -= RB_X; }
    else                       { s = wp; d = g_wp32; blk -= RB_X + RB_WA; }
    int i4 = (blk * 256 + threadIdx.x) * 4;
    float4 v = *(const float4*)(s + i4);
    v.x = rnd_tf32(v.x); v.y = rnd_tf32(v.y);
    v.z = rnd_tf32(v.z); v.w = rnd_tf32(v.w);
    *(float4*)(d + i4) = v;
}

// q-scale: (1/sqrt(64)) * log2(e) — softmax runs in base-2 domain
#define QSCALE 0.18033688011112042f

__device__ __forceinline__ void scat_qkv(int m, int n, float v0, float v1) {
    int b = m >> 11;
    int t = m & 2047;
    int which = n / NC;
    int r = n - which * NC;
    int h = r >> 6;
    int d = r & 63;
    float* dst = (which == 0) ? g_q : (which == 1) ? g_k : g_v;
    float s = (which == 0) ? QSCALE : 1.0f;
    *(float2*)(dst + (((size_t)b * NH + h) * NT + t) * ND + d) =
        make_float2(rnd_tf32(v0 * s), rnd_tf32(v1 * s));
}

// ---------------------------------------------------------------------------
// 128x128 TF32 NT GEMM: 8 warps as 2m x 4n, warp tile 64x32, BK=32.
// 3-stage cp.async pipeline, 1 barrier/chunk. A-frags consumed immediately.
// MODE 0: A=g_x32, B=g_wa32, scatter -> q/k/v   MODE 1: A=g_y, B=g_wp32 -> Cout
// ---------------------------------------------------------------------------
#define QA_STG (128 * 36)
#define QSTAGE (2 * QA_STG)
#define QKV_SMEM (3 * QSTAGE * 4)      // 110592 bytes -> 2 CTAs/SM

template<int MODE>
__global__ void __launch_bounds__(256, 2)
gemm128(float* __restrict__ Cout)
{
    extern __shared__ __align__(16) float fs[];
    constexpr int K = NC;              // 768

    const float* Ag = (MODE == 0) ? g_x32  : g_y;
    const float* Bg = (MODE == 0) ? g_wa32 : g_wp32;

    const uint32_t sb = smem_to_u32(fs);
    const int m0 = blockIdx.y * 128;
    const int n0 = blockIdx.x * 128;
    const int tid = threadIdx.x;
    const int wid = tid >> 5, lane = tid & 31;
    const int g = lane >> 2, t = lane & 3;
    const int wm = wid >> 2, wn = wid & 3;   // 2m x 4n

    const int lrow = tid >> 3, lc4 = (tid & 7) * 4;

    auto load_stage = [&](int s, int k0) {
        #pragma unroll
        for (int i = 0; i < 4; i++) {
            int row = lrow + i * 32;
            cp_async16(sb + (uint32_t)(s * QSTAGE + row * 36 + lc4) * 4,
                       Ag + (size_t)(m0 + row) * K + k0 + lc4);
        }
        #pragma unroll
        for (int i = 0; i < 4; i++) {
            int row = lrow + i * 32;
            cp_async16(sb + (uint32_t)(s * QSTAGE + QA_STG + row * 36 + lc4) * 4,
                       Bg + (size_t)(n0 + row) * K + k0 + lc4);
        }
        cp_commit();
    };

    float acc[4][4][4];
    #pragma unroll
    for (int mt = 0; mt < 4; mt++)
        #pragma unroll
        for (int nt = 0; nt < 4; nt++)
            #pragma unroll
            for (int i = 0; i < 4; i++) acc[mt][nt][i] = 0.0f;

    const int NK = K / 32;             // 24
    load_stage(0, 0);
    load_stage(1, 32);

    for (int c = 0; c < NK; c += 3) {
        #pragma unroll
        for (int u = 0; u < 3; u++) {
            const int cc = c + u;
            cp_wait1();
            __syncthreads();
            if (cc + 2 < NK) load_stage((u + 2) % 3, (cc + 2) * 32);
            else             cp_commit();

            const unsigned* As = (const unsigned*)fs + u * QSTAGE;
            const unsigned* Bs = As + QA_STG;

            #pragma unroll
            for (int ks = 0; ks < 4; ks++) {
                const int ko = ks * 8;
                unsigned b[4][2];
                #pragma unroll
                for (int nt = 0; nt < 4; nt++) {
                    int bb = (wn * 32 + nt * 8 + g) * 36 + ko + t;
                    b[nt][0] = Bs[bb];
                    b[nt][1] = Bs[bb + 4];
                }
                #pragma unroll
                for (int mt = 0; mt < 4; mt++) {
                    unsigned a[4];
                    int base = (wm * 64 + mt * 16 + g) * 36 + ko + t;
                    a[0] = As[base];
                    a[1] = As[base + 8 * 36];
                    a[2] = As[base + 4];
                    a[3] = As[base + 8 * 36 + 4];
                    #pragma unroll
                    for (int nt = 0; nt < 4; nt++)
                        mma_tf32(acc[mt][nt], a, b[nt][0], b[nt][1]);
                }
            }
        }
    }

    #pragma unroll
    for (int mt = 0; mt < 4; mt++) {
        int r0 = m0 + wm * 64 + mt * 16 + g;
        int r1 = r0 + 8;
        #pragma unroll
        for (int nt = 0; nt < 4; nt++) {
            int c = n0 + wn * 32 + nt * 8 + 2 * t;
            if (MODE == 0) {
                scat_qkv(r0, c, acc[mt][nt][0], acc[mt][nt][1]);
                scat_qkv(r1, c, acc[mt][nt][2], acc[mt][nt][3]);
            } else {
                *(float2*)(Cout + (size_t)r0 * NC + c) =
                    make_float2(acc[mt][nt][0], acc[mt][nt][1]);
                *(float2*)(Cout + (size_t)r1 * NC + c) =
                    make_float2(acc[mt][nt][2], acc[mt][nt][3]);
            }
        }
    }
}

// ---------------------------------------------------------------------------
// Flash attention, tf32 mma.sync. Base-2 softmax (q pre-scaled by
// 0.125*log2e); bare MUFU EX2, no FMUL in the exp chain. Otherwise R16.
// ---------------------------------------------------------------------------
#define AQ_U   (128 * 68)
#define AKV_K  0
#define AKV_V  (64 * 68)
#define AKV_STG (64 * 68 + 64 * 72)
#define ATTN_U (AQ_U + 2 * AKV_STG)
#define ATTN_SMEM (ATTN_U * 4)          // 106496 bytes -> 2 CTAs/SM

__global__ void __launch_bounds__(256, 2) attn_mma()
{
    extern __shared__ __align__(16) unsigned su[];
    const uint32_t sb = smem_to_u32(su);
    unsigned* Qs = su;

    const int qt = (int)gridDim.x - 1 - (int)blockIdx.x;
    const int bh = blockIdx.y;
    const int b = bh / NH;
    const int h = bh - b * NH;
    const int tid = threadIdx.x;
    const int wid = tid >> 5, lane = tid & 31;
    const int g = lane >> 2, t = lane & 3;
    const int R = wid * 16;
    const int odd = t & 1;
    const int srcA = (lane & ~3) | (t >> 1);
    const int srcB = srcA + 2;

    const size_t head_base = ((size_t)b * NH + h) * (size_t)NT * ND;
    const int q0 = qt * 128;

    {
        const float* qg = g_q + head_base + (size_t)q0 * ND;
        #pragma unroll
        for (int i = 0; i < 8; i++) {
            int idx = tid + i * 256;
            int row = idx >> 4, d4 = (idx & 15) << 2;
            *(uint4*)(Qs + row * 68 + d4) = *(const uint4*)(qg + row * ND + d4);
        }
    }

    const int kt_max = 2 * qt + 1;

    auto issue_kv = [&](int s, int k0) {
        const float* kg = g_k + head_base + (size_t)k0 * ND;
        const float* vg = g_v + head_base + (size_t)k0 * ND;
        #pragma unroll
        for (int i = 0; i < 4; i++) {
            int idx = tid + i * 256;
            int row = idx >> 4, c4 = (idx & 15) << 2;
            cp_async16(sb + (uint32_t)(AQ_U + s * AKV_STG + AKV_K + row * 68 + c4) * 4,
                       kg + row * ND + c4);
            cp_async16(sb + (uint32_t)(AQ_U + s * AKV_STG + AKV_V + row * 72 + c4) * 4,
                       vg + row * ND + c4);
        }
        cp_commit();
    };

    issue_kv(0, 0);

    float mrow[2] = {-1e30f, -1e30f};
    float lrow[2] = {0.0f, 0.0f};
    float o[8][4];
    #pragma unroll
    for (int nt = 0; nt < 8; nt++)
        #pragma unroll
        for (int i = 0; i < 4; i++) o[nt][i] = 0.0f;

    for (int kt = 0; kt <= kt_max; kt++) {
        cp_wait0();
        __syncthreads();
        if (kt + 1 <= kt_max) issue_kv((kt + 1) & 1, (kt + 1) * 64);

        const unsigned* Ks = su + AQ_U + (kt & 1) * AKV_STG + AKV_K;
        const unsigned* Vs = su + AQ_U + (kt & 1) * AKV_STG + AKV_V;
        const int k0 = kt * 64;

        // ---- S = Q K^T  (base-2 logits; q pre-scaled) ----
        float sc[8][4];
        #pragma unroll
        for (int nt = 0; nt < 8; nt++)
            #pragma unroll
            for (int i = 0; i < 4; i++) sc[nt][i] = 0.0f;

        #pragma unroll
        for (int ks = 0; ks < 8; ks++) {
            unsigned a[4];
            int ra = (R + g) * 68 + ks * 8 + t;
            int rb = (R + g + 8) * 68 + ks * 8 + t;
            a[0] = Qs[ra]; a[1] = Qs[rb]; a[2] = Qs[ra + 4]; a[3] = Qs[rb + 4];
            #pragma unroll
            for (int nt = 0; nt < 8; nt++) {
                int kb = (nt * 8 + g) * 68 + ks * 8 + t;
                mma_tf32(sc[nt], a, Ks[kb], Ks[kb + 4]);
            }
        }

        // ---- causal mask ----
        const bool nm = (kt >= 2 * qt);
        if (nm) {
            const int rlo = q0 + R + g;
            const int rhi = rlo + 8;
            #pragma unroll
            for (int nt = 0; nt < 8; nt++) {
                int cc = k0 + nt * 8 + 2 * t;
                if (cc > rlo)     sc[nt][0] = -1e30f;
                if (cc + 1 > rlo) sc[nt][1] = -1e30f;
                if (cc > rhi)     sc[nt][2] = -1e30f;
                if (cc + 1 > rhi) sc[nt][3] = -1e30f;
            }
        }

        // ---- online softmax (base 2) ----
        float mx0 = -1e30f, mx1 = -1e30f;
        #pragma unroll
        for (int nt = 0; nt < 8; nt++) {
            mx0 = fmaxf(mx0, fmaxf(sc[nt][0], sc[nt][1]));
            mx1 = fmaxf(mx1, fmaxf(sc[nt][2], sc[nt][3]));
        }
        mx0 = fmaxf(mx0, __shfl_xor_sync(0xffffffffu, mx0, 1));
        mx0 = fmaxf(mx0, __shfl_xor_sync(0xffffffffu, mx0, 2));
        mx1 = fmaxf(mx1, __shfl_xor_sync(0xffffffffu, mx1, 1));
        mx1 = fmaxf(mx1, __shfl_xor_sync(0xffffffffu, mx1, 2));

        float mn0 = fmaxf(mrow[0], mx0);
        float mn1 = fmaxf(mrow[1], mx1);
        float al0 = ex2(mrow[0] - mn0);
        float al1 = ex2(mrow[1] - mn1);
        mrow[0] = mn0; mrow[1] = mn1;

        float rs0 = 0.0f, rs1 = 0.0f;
        #pragma unroll
        for (int nt = 0; nt < 8; nt++) {
            sc[nt][0] = ex2(sc[nt][0] - mn0); rs0 += sc[nt][0];
            sc[nt][1] = ex2(sc[nt][1] - mn0); rs0 += sc[nt][1];
            sc[nt][2] = ex2(sc[nt][2] - mn1); rs1 += sc[nt][2];
            sc[nt][3] = ex2(sc[nt][3] - mn1); rs1 += sc[nt][3];
        }
        rs0 += __shfl_xor_sync(0xffffffffu, rs0, 1);
        rs0 += __shfl_xor_sync(0xffffffffu, rs0, 2);
        rs1 += __shfl_xor_sync(0xffffffffu, rs1, 1);
        rs1 += __shfl_xor_sync(0xffffffffu, rs1, 2);
        lrow[0] = lrow[0] * al0 + rs0;
        lrow[1] = lrow[1] * al1 + rs1;

        #pragma unroll
        for (int nt = 0; nt < 8; nt++) {
            o[nt][0] *= al0; o[nt][1] *= al0;
            o[nt][2] *= al1; o[nt][3] *= al1;
        }

        // ---- O += P V : P A-fragments via intra-quad shuffle ----
        #pragma unroll
        for (int ks = 0; ks < 8; ks++) {
            unsigned p0 = f2tf32(sc[ks][0]);
            unsigned p1 = f2tf32(sc[ks][1]);
            unsigned p2 = f2tf32(sc[ks][2]);
            unsigned p3 = f2tf32(sc[ks][3]);
            unsigned u0 = __shfl_sync(0xffffffffu, p0, srcA);
            unsigned u1 = __shfl_sync(0xffffffffu, p1, srcA);
            unsigned u2 = __shfl_sync(0xffffffffu, p2, srcA);
            unsigned u3 = __shfl_sync(0xffffffffu, p3, srcA);
            unsigned w0 = __shfl_sync(0xffffffffu, p0, srcB);
            unsigned w1 = __shfl_sync(0xffffffffu, p1, srcB);
            unsigned w2 = __shfl_sync(0xffffffffu, p2, srcB);
            unsigned w3 = __shfl_sync(0xffffffffu, p3, srcB);
            unsigned a[4];
            a[0] = odd ? u1 : u0;
            a[1] = odd ? u3 : u2;
            a[2] = odd ? w1 : w0;
            a[3] = odd ? w3 : w2;
            #pragma unroll
            for (int nt = 0; nt < 8; nt++) {
                int v0 = (ks * 8 + t) * 72 + nt * 8 + g;
                int v1 = (ks * 8 + t + 4) * 72 + nt * 8 + g;
                mma_tf32(o[nt], a, Vs[v0], Vs[v1]);
            }
        }
    }

    float i0 = 1.0f / lrow[0];
    float i1 = 1.0f / lrow[1];
    size_t base0 = ((size_t)b * NT + (q0 + R + g)) * NC + h * ND;
    size_t base1 = ((size_t)b * NT + (q0 + R + g + 8)) * NC + h * ND;
    #pragma unroll
    for (int nt = 0; nt < 8; nt++) {
        size_t off0 = base0 + nt * 8 + 2 * t;
        size_t off1 = base1 + nt * 8 + 2 * t;
        *(float2*)(g_y + off0) = make_float2(rnd_tf32(o[nt][0] * i0),
                                             rnd_tf32(o[nt][1] * i0));
        *(float2*)(g_y + off1) = make_float2(rnd_tf32(o[nt][2] * i1),
                                             rnd_tf32(o[nt][3] * i1));
    }
}

// ---------------------------------------------------------------------------
extern "C" void kernel_launch(void* const* d_in, const int* in_sizes, int n_in,
                              void* d_out, int out_size)
{
    const float* x  = nullptr;   // 3145728
    const float* Wa = nullptr;   // 1769472
    const float* Wp = nullptr;   // 589824
    for (int i = 0; i < n_in; i++) {
        if (in_sizes[i] == NB * NT * NC)      x  = (const float*)d_in[i];
        else if (in_sizes[i] == 3 * NC * NC)  Wa = (const float*)d_in[i];
        else if (in_sizes[i] == NC * NC)      Wp = (const float*)d_in[i];
    }
    float* out = (float*)d_out;

    cudaFuncSetAttribute(attn_mma,
                         cudaFuncAttributeMaxDynamicSharedMemorySize, ATTN_SMEM);
    cudaFuncSetAttribute(gemm128<0>,
                         cudaFuncAttributeMaxDynamicSharedMemorySize, QKV_SMEM);
    cudaFuncSetAttribute(gemm128<1>,
                         cudaFuncAttributeMaxDynamicSharedMemorySize, QKV_SMEM);

    // 0) fused one-time rna-tf32 rounding
    round_all<<<RB_X + RB_WA + RB_WP, 256>>>(x, Wa, Wp);

    // 1) QKV projection (128x128), scatter q(*0.125*log2e)/k/v
    gemm128<0><<<dim3(3 * NC / 128, NB * NT / 128), 256, QKV_SMEM>>>(nullptr);

    // 2) causal flash attention (base-2 softmax) -> g_y
    attn_mma<<<dim3(NT / 128, NB * NH), 256, ATTN_SMEM>>>();

    // 3) output projection (128x128, single wave)
    gemm128<1><<<dim3(NC / 128, NB * NT / 128), 256, QKV_SMEM>>>(out);
}